// round 6
// baseline (speedup 1.0000x reference)
#include <cuda_runtime.h>
#include <cstdint>

#define NV 4096
#define F1 512
#define FH 256
#define NHEADS 4
#define F2 1024   // nhid * nheads
#define FO 256
#define NW (NV/32) // 128 bitmask words per row

#define PSROW 36   // gemm A tile stride
#define WROW  264  // Wh tile row stride (floats): 264%32==8 -> conflict-free B frags
#define PS2   40   // attn P tile stride (pair-packed): conflict-free LDS.64 A frags

// ---------------- scratch (static device memory; no allocations) ------------
__device__ __align__(16) float  g_Wh1[NHEADS * NV * FH]; // 16 MB
__device__ __align__(16) float  g_h1[NV * F2];           // 16 MB
__device__ __align__(16) float  g_Wh2[NV * FO];          // 4 MB
__device__ __align__(16) float4 g_sT1[NHEADS * NV];      // (s, e^s, e^.2s, _)
__device__ __align__(16) float  g_dst1[NHEADS * NV];     // raw d
__device__ __align__(16) float2 g_ed1[NHEADS * NV];      // (e^d, e^.2d)
__device__ __align__(16) float4 g_sT2[NV];
__device__ __align__(16) float  g_dst2[NV];
__device__ __align__(16) float2 g_ed2[NV];
__device__ __align__(16) float  g_np[2 * NV * FO];       // L1 split numerators
__device__ __align__(16) float  g_lp[2 * NV];            // L1 split denominators
__device__ __align__(16) unsigned g_adjbits[NV * NW];    // 2 MB

// ---------------- tf32 mma helpers ------------------------------------------
__device__ __forceinline__ float tf32r(float x) {
    uint32_t u;
    asm("cvt.rna.tf32.f32 %0, %1;" : "=r"(u) : "f"(x));
    return __uint_as_float(u);
}
__device__ __forceinline__ void mma_tf32(float* d, const uint32_t* a,
                                         uint32_t b0, uint32_t b1) {
    asm volatile(
        "mma.sync.aligned.m16n8k8.row.col.f32.tf32.tf32.f32 "
        "{%0,%1,%2,%3}, {%4,%5,%6,%7}, {%8,%9}, {%0,%1,%2,%3};"
        : "+f"(d[0]), "+f"(d[1]), "+f"(d[2]), "+f"(d[3])
        : "r"(a[0]), "r"(a[1]), "r"(a[2]), "r"(a[3]), "r"(b0), "r"(b1));
}

// ---------------- K0: adjacency -> bitmask ----------------------------------
__global__ void adjbits_kernel(const int* __restrict__ adj) {
    int idx = blockIdx.x * blockDim.x + threadIdx.x;   // over NV*NV
    unsigned bit = (adj[idx] != 0) ? 1u : 0u;
    unsigned w = __ballot_sync(0xffffffffu, bit);
    if ((threadIdx.x & 31) == 0) g_adjbits[idx >> 5] = w;
}

// ---------------- K1: tf32 mma GEMM  C[*,256] = A[*,K] @ B[K,256] ------------
template <int ROWS>
__global__ void __launch_bounds__(512, 1)
gemm_tf32_kernel(const float* __restrict__ A, const float* __restrict__ B,
                 float* __restrict__ C, int K, long bStride, long cStride) {
    constexpr int MT = ROWS / 64;
    constexpr int TPR = 512 / ROWS;     // threads per A-row
    constexpr int AK  = 32 / TPR;       // A cols per thread
    extern __shared__ char smem[];
    float* As = (float*)smem;                            // [2][ROWS*PSROW]
    float* Bs = (float*)(smem + 2 * ROWS * PSROW * 4);   // [2][32*WROW]

    const int tid = threadIdx.x;
    const int wid = tid >> 5, lane = tid & 31;
    const int wr = wid >> 2, wc = wid & 3;
    const float* Bb = B + (size_t)blockIdx.y * bStride;
    float* Cb = C + (size_t)blockIdx.y * cStride;
    const int i0 = blockIdx.x * ROWS;

    const int arow = tid / TPR, ak0 = (tid % TPR) * AK;
    const int jrow = tid >> 4, fbase = (tid & 15) * 4;
    const int ar = lane >> 2, ak = lane & 3;

    float d[MT][8][4];
#pragma unroll
    for (int mt = 0; mt < MT; mt++)
#pragma unroll
        for (int nt = 0; nt < 8; nt++)
#pragma unroll
            for (int v = 0; v < 4; v++) d[mt][nt][v] = 0.f;

    const int NKT = K / 32;
    for (int kt = 0; kt < NKT; kt++) {
        const int bb = kt & 1;
        const int k0g = kt * 32;
        {
            const float* wp = Bb + (size_t)(k0g + jrow) * FH + fbase;
            float* bs = Bs + bb * 32 * WROW + jrow * WROW + fbase;
#pragma unroll
            for (int q = 0; q < 4; q++) {
                float4 v = *(const float4*)(wp + 64 * q);
                *(float4*)(bs + 64 * q) =
                    make_float4(tf32r(v.x), tf32r(v.y), tf32r(v.z), tf32r(v.w));
            }
            const float* ap = A + (size_t)(i0 + arow) * K + k0g + ak0;
            float* as = As + bb * ROWS * PSROW + arow * PSROW + ak0;
#pragma unroll
            for (int q = 0; q < AK / 4; q++) {
                float4 v = *(const float4*)(ap + 4 * q);
                *(float4*)(as + 4 * q) =
                    make_float4(tf32r(v.x), tf32r(v.y), tf32r(v.z), tf32r(v.w));
            }
        }
        __syncthreads();
        const float* pB = As + bb * ROWS * PSROW;
        const float* wB = Bs + bb * 32 * WROW;
#pragma unroll
        for (int kk = 0; kk < 4; kk++) {
            const int k0 = kk * 8;
            uint32_t a[MT][4];
#pragma unroll
            for (int mt = 0; mt < MT; mt++) {
                const float* pr = pB + (wr * 16 * MT + mt * 16 + ar) * PSROW + k0 + ak;
                a[mt][0] = __float_as_uint(pr[0]);
                a[mt][1] = __float_as_uint(pr[8 * PSROW]);
                a[mt][2] = __float_as_uint(pr[4]);
                a[mt][3] = __float_as_uint(pr[8 * PSROW + 4]);
            }
#pragma unroll
            for (int nt = 0; nt < 8; nt++) {
                const int n = wc * 64 + nt * 8 + ar;
                uint32_t b0 = __float_as_uint(wB[(k0 + ak) * WROW + n]);
                uint32_t b1 = __float_as_uint(wB[(k0 + ak + 4) * WROW + n]);
#pragma unroll
                for (int mt = 0; mt < MT; mt++)
                    mma_tf32(d[mt][nt], a[mt], b0, b1);
            }
        }
        __syncthreads();
    }
#pragma unroll
    for (int mt = 0; mt < MT; mt++) {
        const int r0 = wr * 16 * MT + mt * 16 + ar;
        const int r1 = r0 + 8;
#pragma unroll
        for (int nt = 0; nt < 8; nt++) {
            const int c = wc * 64 + nt * 8 + 2 * ak;
            *(float2*)(Cb + (size_t)(i0 + r0) * FH + c) = make_float2(d[mt][nt][0], d[mt][nt][1]);
            *(float2*)(Cb + (size_t)(i0 + r1) * FH + c) = make_float2(d[mt][nt][2], d[mt][nt][3]);
        }
    }
}

#define GEMM_SMEM(R) (2 * (R) * PSROW * 4 + 2 * 32 * WROW * 4)

// ---------------- K2: src/dst projections + exp tables -----------------------
__global__ void srcdst_kernel(const float* __restrict__ avec, int layer) {
    __shared__ float sa[2 * FH];
    const int b = blockIdx.y;
    const float* Wh = layer ? g_Wh2 : g_Wh1 + (size_t)b * NV * FH;
    const float* a  = avec + b * 2 * FH;
    float4* sT = layer ? g_sT2  : g_sT1  + b * NV;
    float*  dR = layer ? g_dst2 : g_dst1 + b * NV;
    float2* ed = layer ? g_ed2  : g_ed1  + b * NV;

    const int tid = threadIdx.x;
    for (int i = tid; i < 2 * FH; i += blockDim.x) sa[i] = a[i];
    __syncthreads();

    const int warp = tid >> 5, lane = tid & 31;
    const int row = blockIdx.x * 8 + warp;
    const float* wr = Wh + (size_t)row * FH;
    float s1 = 0.f, s2 = 0.f;
#pragma unroll
    for (int v = lane; v < FH; v += 32) {
        float w = wr[v];
        s1 += w * sa[v];
        s2 += w * sa[FH + v];
    }
#pragma unroll
    for (int o = 16; o; o >>= 1) {
        s1 += __shfl_xor_sync(0xffffffffu, s1, o);
        s2 += __shfl_xor_sync(0xffffffffu, s2, o);
    }
    if (lane == 0) {
        sT[row] = make_float4(s1, __expf(s1), __expf(0.2f * s1), 0.f);
        dR[row] = s2;
        ed[row] = make_float2(__expf(s2), __expf(0.2f * s2));
    }
}

// ---------------- K3: tf32 mma fused attention -------------------------------
// ROWS=64, 256 threads, 8 warps (2x4), 2 CTAs/SM. R4-style pipeline:
// fill(kt+1) -> MMA(kt) -> sync, double-buffered. Exp-free P via tables.
#define AROWS 64
#define ATTN_SMEM (2 * AROWS * PS2 * 4 + 2 * 32 * WROW * 4 + 256 * 4)

template <int PARTIAL>
__device__ __forceinline__ float attn_fill(
    float* Pb, float* Wb, int kt,
    const float* __restrict__ Wh, const float* __restrict__ dR,
    const float2* __restrict__ edT, const unsigned* __restrict__ adjrow,
    float4 sv, int jbase, int prow, int kk, int jrow, int fcol) {
    const int j0 = jbase + kt * 32;
    const int kb = kk * 8;
    // Wh tile: 32 j-rows x 256 f, each thread 8 float4
    const float* wp = Wh + (size_t)(j0 + jrow) * FH + fcol;
    float4 wv[8];
#pragma unroll
    for (int q = 0; q < 8; q++) wv[q] = *(const float4*)(wp + 32 * q);
    // P values for row prow, k = kb..kb+7
    unsigned aw = adjrow[kt] >> kb;
    float4 d0 = *(const float4*)(dR + j0 + kb);
    float4 d1 = *(const float4*)(dR + j0 + kb + 4);
    float dv[8] = {d0.x, d0.y, d0.z, d0.w, d1.x, d1.y, d1.z, d1.w};
    float2 ev[8];
#pragma unroll
    for (int g = 0; g < 4; g++) {
        float4 t = *(const float4*)(edT + j0 + kb + 2 * g);
        ev[2*g]   = make_float2(t.x, t.y);
        ev[2*g+1] = make_float2(t.z, t.w);
    }
    float lsum = 0.f;
    float pv[8];
#pragma unroll
    for (int u = 0; u < 8; u++) {
        bool hot = (sv.x + dv[u]) > 0.f;
        float p = (hot ? sv.y : sv.z) * (hot ? ev[u].x : ev[u].y);
        p = ((aw >> u) & 1u) ? p : 0.f;
        p = tf32r(p);
        lsum += p;
        pv[u] = p;
    }
    // pair-packed store: col kb + 2c holds (p[kb+c], p[kb+c+4])
    float2* pb = (float2*)(Pb + prow * PS2 + kb);
#pragma unroll
    for (int c = 0; c < 4; c++) pb[c] = make_float2(pv[c], pv[c + 4]);
    // Wh store
    float* bs = Wb + jrow * WROW + fcol;
#pragma unroll
    for (int q = 0; q < 8; q++)
        *(float4*)(bs + 32 * q) =
            make_float4(tf32r(wv[q].x), tf32r(wv[q].y), tf32r(wv[q].z), tf32r(wv[q].w));
    return lsum;
}

template <int PARTIAL>
__global__ void __launch_bounds__(256, 2)
attn_kernel(float* __restrict__ unused) {
    extern __shared__ char smem[];
    float* Ps    = (float*)smem;                          // [2][64*PS2]
    float* Whs   = (float*)(smem + 2 * AROWS * PS2 * 4);  // [2][32*WROW]
    float* lpart = (float*)(smem + 2 * AROWS * PS2 * 4 + 2 * 32 * WROW * 4);

    const int tid = threadIdx.x;
    const int wid = tid >> 5, lane = tid & 31;
    const int wr = wid >> 2, wc = wid & 3;   // 2 x 4 warp grid
    const int i0 = blockIdx.x * AROWS;

    const float* Wh; const float4* sT; const float* dR; const float2* edT;
    int jbase, NKT;
    if (PARTIAL) {
        Wh = g_Wh2; sT = g_sT2; dR = g_dst2; edT = g_ed2;
        jbase = blockIdx.y * (NV / 2); NKT = (NV / 2) / 32;
    } else {
        const int b = blockIdx.z;
        Wh = g_Wh1 + (size_t)b * NV * FH;
        sT = g_sT1 + b * NV; dR = g_dst1 + b * NV; edT = g_ed1 + b * NV;
        jbase = 0; NKT = NV / 32;
    }

    const int prow = tid >> 2;         // 0..63
    const int kk_f = tid & 3;          // fill k-group
    const float4 sv = sT[i0 + prow];
    const unsigned* adjrow = g_adjbits + (size_t)(i0 + prow) * NW + (jbase >> 5);
    const int jrow = tid >> 3, fcol = (tid & 7) * 4;
    const int ar = lane >> 2, ak = lane & 3;

    float d[2][8][4];
#pragma unroll
    for (int mt = 0; mt < 2; mt++)
#pragma unroll
        for (int nt = 0; nt < 8; nt++)
#pragma unroll
            for (int v = 0; v < 4; v++) d[mt][nt][v] = 0.f;

    float lsum = attn_fill<PARTIAL>(Ps, Whs, 0, Wh, dR, edT, adjrow, sv,
                                    jbase, prow, kk_f, jrow, fcol);
    __syncthreads();

    for (int kt = 0; kt < NKT; kt++) {
        const int bb = kt & 1;
        if (kt + 1 < NKT)
            lsum += attn_fill<PARTIAL>(Ps + (bb ^ 1) * AROWS * PS2,
                                       Whs + (bb ^ 1) * 32 * WROW,
                                       kt + 1, Wh, dR, edT, adjrow, sv,
                                       jbase, prow, kk_f, jrow, fcol);
        const float* pB = Ps + bb * AROWS * PS2;
        const float* wB = Whs + bb * 32 * WROW;
#pragma unroll
        for (int kk = 0; kk < 4; kk++) {
            const int k0 = kk * 8;
            uint32_t a[2][4];
#pragma unroll
            for (int mt = 0; mt < 2; mt++) {
                const float* pr = pB + (wr * 32 + mt * 16 + ar) * PS2 + k0 + 2 * ak;
                float2 q0 = *(const float2*)pr;
                float2 q1 = *(const float2*)(pr + 8 * PS2);
                a[mt][0] = __float_as_uint(q0.x);
                a[mt][1] = __float_as_uint(q1.x);
                a[mt][2] = __float_as_uint(q0.y);
                a[mt][3] = __float_as_uint(q1.y);
            }
#pragma unroll
            for (int nt = 0; nt < 8; nt++) {
                const int n = wc * 64 + nt * 8 + ar;
                uint32_t b0 = __float_as_uint(wB[(k0 + ak) * WROW + n]);
                uint32_t b1 = __float_as_uint(wB[(k0 + ak + 4) * WROW + n]);
                mma_tf32(d[0][nt], a[0], b0, b1);
                mma_tf32(d[1][nt], a[1], b0, b1);
            }
        }
        __syncthreads();
    }
    lpart[tid] = lsum;   // lpart[prow*4 + kk_f]
    __syncthreads();

    if (PARTIAL) {
        float* np = g_np + (size_t)blockIdx.y * NV * FO;
#pragma unroll
        for (int mt = 0; mt < 2; mt++) {
            const int r0 = wr * 32 + mt * 16 + ar;
            const int r1 = r0 + 8;
#pragma unroll
            for (int nt = 0; nt < 8; nt++) {
                const int c = wc * 64 + nt * 8 + 2 * ak;
                *(float2*)(np + (size_t)(i0 + r0) * FO + c) = make_float2(d[mt][nt][0], d[mt][nt][1]);
                *(float2*)(np + (size_t)(i0 + r1) * FO + c) = make_float2(d[mt][nt][2], d[mt][nt][3]);
            }
        }
        if (tid < AROWS) {
            float l = lpart[tid * 4] + lpart[tid * 4 + 1] +
                      lpart[tid * 4 + 2] + lpart[tid * 4 + 3];
            g_lp[blockIdx.y * NV + i0 + tid] = l;
        }
    } else {
        float* out = g_h1;
        const int coloff = blockIdx.z * FH;
#pragma unroll
        for (int mt = 0; mt < 2; mt++) {
            const int r0 = wr * 32 + mt * 16 + ar;
            const int r1 = r0 + 8;
            const float l0 = lpart[r0*4] + lpart[r0*4+1] + lpart[r0*4+2] + lpart[r0*4+3];
            const float l1 = lpart[r1*4] + lpart[r1*4+1] + lpart[r1*4+2] + lpart[r1*4+3];
            const float rl0 = 1.0f / l0, rl1 = 1.0f / l1;
#pragma unroll
            for (int nt = 0; nt < 8; nt++) {
                const int c = coloff + wc * 64 + nt * 8 + 2 * ak;
                float o0 = d[mt][nt][0] * rl0, o1 = d[mt][nt][1] * rl0;
                float o2 = d[mt][nt][2] * rl1, o3 = d[mt][nt][3] * rl1;
                o0 = o0 > 0.f ? o0 : (__expf(o0) - 1.0f);
                o1 = o1 > 0.f ? o1 : (__expf(o1) - 1.0f);
                o2 = o2 > 0.f ? o2 : (__expf(o2) - 1.0f);
                o3 = o3 > 0.f ? o3 : (__expf(o3) - 1.0f);
                *(float2*)(out + (size_t)(i0 + r0) * F2 + c) = make_float2(o0, o1);
                *(float2*)(out + (size_t)(i0 + r1) * F2 + c) = make_float2(o2, o3);
            }
        }
    }
}

// ---------------- K4: combine split partials (layer 1 epilogue) --------------
__global__ void combine_kernel(float* __restrict__ out) {
    const int i = blockIdx.x;
    const int c = threadIdx.x;
    const float l = g_lp[i] + g_lp[NV + i];
    const float n = g_np[(size_t)i * FO + c] +
                    g_np[(size_t)NV * FO + (size_t)i * FO + c];
    out[(size_t)i * FO + c] = n / l;
}

// ---------------- launch -----------------------------------------------------
extern "C" void kernel_launch(void* const* d_in, const int* in_sizes, int n_in,
                              void* d_out, int out_size) {
    (void)in_sizes; (void)n_in; (void)out_size;
    const float* x   = (const float*)d_in[0];
    const int*   adj = (const int*)d_in[1];
    const float* W1  = (const float*)d_in[2];
    const float* a1  = (const float*)d_in[3];
    const float* W2  = (const float*)d_in[4];
    const float* a2  = (const float*)d_in[5];
    float* out = (float*)d_out;

    static int inited = 0;
    if (!inited) {
        cudaFuncSetAttribute(gemm_tf32_kernel<128>,
            cudaFuncAttributeMaxDynamicSharedMemorySize, GEMM_SMEM(128));
        cudaFuncSetAttribute(gemm_tf32_kernel<64>,
            cudaFuncAttributeMaxDynamicSharedMemorySize, GEMM_SMEM(64));
        cudaFuncSetAttribute(attn_kernel<0>,
            cudaFuncAttributeMaxDynamicSharedMemorySize, ATTN_SMEM);
        cudaFuncSetAttribute(attn_kernel<1>,
            cudaFuncAttributeMaxDynamicSharedMemorySize, ATTN_SMEM);
        inited = 1;
    }

    float* Wh1p; cudaGetSymbolAddress((void**)&Wh1p, g_Wh1);
    float* h1p;  cudaGetSymbolAddress((void**)&h1p,  g_h1);
    float* Wh2p; cudaGetSymbolAddress((void**)&Wh2p, g_Wh2);

    adjbits_kernel<<<(NV * NV) / 256, 256>>>(adj);
    gemm_tf32_kernel<128><<<dim3(NV / 128, NHEADS), 512, GEMM_SMEM(128)>>>(
        x, W1, Wh1p, F1, (long)F1 * FH, (long)NV * FH);
    srcdst_kernel<<<dim3(NV / 8, NHEADS), 256>>>(a1, 0);
    attn_kernel<0><<<dim3(NV / AROWS, 1, NHEADS), 256, ATTN_SMEM>>>(nullptr);
    gemm_tf32_kernel<64><<<dim3(NV / 64, 1), 512, GEMM_SMEM(64)>>>(
        h1p, W2, Wh2p, F2, 0L, 0L);
    srcdst_kernel<<<dim3(NV / 8, 1), 256>>>(a2, 1);
    attn_kernel<1><<<dim3(NV / AROWS, 2), 256, ATTN_SMEM>>>(nullptr);
    combine_kernel<<<NV, 256>>>(out);
}

// round 7
// speedup vs baseline: 1.7109x; 1.7109x over previous
#include <cuda_runtime.h>
#include <cstdint>

#define NV 4096
#define F1 512
#define FH 256
#define NHEADS 4
#define F2 1024   // nhid * nheads
#define FO 256
#define NW (NV/32) // 128 bitmask words per row

#define PSROW 36   // P/A tile row stride: conflict-free 32-bit A frags
#define WROW  264  // Wh/B tile row stride: 264%32==8 -> conflict-free B frags

// ---------------- scratch (static device memory; no allocations) ------------
__device__ __align__(16) float  g_Wh1[NHEADS * NV * FH]; // tf32-rounded
__device__ __align__(16) float  g_h1[NV * F2];
__device__ __align__(16) float  g_Wh2[NV * FO];          // tf32-rounded
__device__ __align__(16) float  g_src1[NHEADS * NV];
__device__ __align__(16) float  g_dst1[NHEADS * NV];
__device__ __align__(16) float  g_src2[NV];
__device__ __align__(16) float  g_dst2[NV];
__device__ __align__(16) float  g_np[2 * NV * FO];       // L1 split numerators
__device__ __align__(16) float  g_lp[2 * NV];            // L1 split denominators
__device__ __align__(16) unsigned g_adjbits[NV * NW];    // 2 MB

// ---------------- tf32 mma / cp.async helpers --------------------------------
__device__ __forceinline__ float tf32r(float x) {
    uint32_t u;
    asm("cvt.rna.tf32.f32 %0, %1;" : "=r"(u) : "f"(x));
    return __uint_as_float(u);
}
__device__ __forceinline__ void mma_tf32(float* d, const uint32_t* a,
                                         uint32_t b0, uint32_t b1) {
    asm volatile(
        "mma.sync.aligned.m16n8k8.row.col.f32.tf32.tf32.f32 "
        "{%0,%1,%2,%3}, {%4,%5,%6,%7}, {%8,%9}, {%0,%1,%2,%3};"
        : "+f"(d[0]), "+f"(d[1]), "+f"(d[2]), "+f"(d[3])
        : "r"(a[0]), "r"(a[1]), "r"(a[2]), "r"(a[3]), "r"(b0), "r"(b1));
}
__device__ __forceinline__ void cp16(uint32_t saddr, const void* gptr) {
    asm volatile("cp.async.cg.shared.global [%0], [%1], 16;"
                 :: "r"(saddr), "l"(gptr));
}
__device__ __forceinline__ void cp_commit() {
    asm volatile("cp.async.commit_group;");
}
__device__ __forceinline__ void cp_wait1() {
    asm volatile("cp.async.wait_group 1;");
}

// ---------------- K0: adjacency -> bitmask ----------------------------------
__global__ void adjbits_kernel(const int* __restrict__ adj) {
    int idx = blockIdx.x * blockDim.x + threadIdx.x;   // over NV*NV
    unsigned bit = (adj[idx] != 0) ? 1u : 0u;
    unsigned w = __ballot_sync(0xffffffffu, bit);
    if ((threadIdx.x & 31) == 0) g_adjbits[idx >> 5] = w;
}

// ---------------- K1: tf32 mma GEMM  C[*,256] = A[*,K] @ B[K,256] ------------
// C is stored tf32-rounded (consumed by attn tensor path; negligible error).
template <int ROWS>
__global__ void __launch_bounds__(512, 1)
gemm_tf32_kernel(const float* __restrict__ A, const float* __restrict__ B,
                 float* __restrict__ C, int K, long bStride, long cStride) {
    constexpr int MT = ROWS / 64;
    constexpr int TPR = 512 / ROWS;     // threads per A-row
    constexpr int AK  = 32 / TPR;       // A cols per thread
    extern __shared__ char smem[];
    float* As = (float*)smem;                            // [2][ROWS*PSROW]
    float* Bs = (float*)(smem + 2 * ROWS * PSROW * 4);   // [2][32*WROW]

    const int tid = threadIdx.x;
    const int wid = tid >> 5, lane = tid & 31;
    const int wr = wid >> 2, wc = wid & 3;
    const float* Bb = B + (size_t)blockIdx.y * bStride;
    float* Cb = C + (size_t)blockIdx.y * cStride;
    const int i0 = blockIdx.x * ROWS;

    const int arow = tid / TPR, ak0 = (tid % TPR) * AK;
    const int jrow = tid >> 4, fbase = (tid & 15) * 4;
    const int ar = lane >> 2, ak = lane & 3;

    float d[MT][8][4];
#pragma unroll
    for (int mt = 0; mt < MT; mt++)
#pragma unroll
        for (int nt = 0; nt < 8; nt++)
#pragma unroll
            for (int v = 0; v < 4; v++) d[mt][nt][v] = 0.f;

    const int NKT = K / 32;
    for (int kt = 0; kt < NKT; kt++) {
        const int bb = kt & 1;
        const int k0g = kt * 32;
        {
            const float* wp = Bb + (size_t)(k0g + jrow) * FH + fbase;
            float* bs = Bs + bb * 32 * WROW + jrow * WROW + fbase;
#pragma unroll
            for (int q = 0; q < 4; q++) {
                float4 v = *(const float4*)(wp + 64 * q);
                *(float4*)(bs + 64 * q) =
                    make_float4(tf32r(v.x), tf32r(v.y), tf32r(v.z), tf32r(v.w));
            }
            const float* ap = A + (size_t)(i0 + arow) * K + k0g + ak0;
            float* as = As + bb * ROWS * PSROW + arow * PSROW + ak0;
#pragma unroll
            for (int q = 0; q < AK / 4; q++) {
                float4 v = *(const float4*)(ap + 4 * q);
                *(float4*)(as + 4 * q) =
                    make_float4(tf32r(v.x), tf32r(v.y), tf32r(v.z), tf32r(v.w));
            }
        }
        __syncthreads();
        const float* pB = As + bb * ROWS * PSROW;
        const float* wB = Bs + bb * 32 * WROW;
#pragma unroll
        for (int kk = 0; kk < 4; kk++) {
            const int k0 = kk * 8;
            uint32_t a[MT][4];
#pragma unroll
            for (int mt = 0; mt < MT; mt++) {
                const float* pr = pB + (wr * 16 * MT + mt * 16 + ar) * PSROW + k0 + ak;
                a[mt][0] = __float_as_uint(pr[0]);
                a[mt][1] = __float_as_uint(pr[8 * PSROW]);
                a[mt][2] = __float_as_uint(pr[4]);
                a[mt][3] = __float_as_uint(pr[8 * PSROW + 4]);
            }
#pragma unroll
            for (int nt = 0; nt < 8; nt++) {
                const int n = wc * 64 + nt * 8 + ar;
                uint32_t b0 = __float_as_uint(wB[(k0 + ak) * WROW + n]);
                uint32_t b1 = __float_as_uint(wB[(k0 + ak + 4) * WROW + n]);
#pragma unroll
                for (int mt = 0; mt < MT; mt++)
                    mma_tf32(d[mt][nt], a[mt], b0, b1);
            }
        }
        __syncthreads();
    }
#pragma unroll
    for (int mt = 0; mt < MT; mt++) {
        const int r0 = wr * 16 * MT + mt * 16 + ar;
        const int r1 = r0 + 8;
#pragma unroll
        for (int nt = 0; nt < 8; nt++) {
            const int c = wc * 64 + nt * 8 + 2 * ak;
            *(float2*)(Cb + (size_t)(i0 + r0) * FH + c) =
                make_float2(tf32r(d[mt][nt][0]), tf32r(d[mt][nt][1]));
            *(float2*)(Cb + (size_t)(i0 + r1) * FH + c) =
                make_float2(tf32r(d[mt][nt][2]), tf32r(d[mt][nt][3]));
        }
    }
}

#define GEMM_SMEM(R) (2 * (R) * PSROW * 4 + 2 * 32 * WROW * 4)

// ---------------- K2: src/dst projections (exact fp32) -----------------------
__global__ void srcdst_kernel(const float* __restrict__ avec, int layer) {
    __shared__ float sa[2 * FH];
    const int b = blockIdx.y;
    const float* Wh = layer ? g_Wh2 : g_Wh1 + (size_t)b * NV * FH;
    const float* a  = avec + b * 2 * FH;
    float* src = layer ? g_src2 : g_src1 + b * NV;
    float* dst = layer ? g_dst2 : g_dst1 + b * NV;

    const int tid = threadIdx.x;
    for (int i = tid; i < 2 * FH; i += blockDim.x) sa[i] = a[i];
    __syncthreads();

    const int warp = tid >> 5, lane = tid & 31;
    const int row = blockIdx.x * 8 + warp;
    const float* wr = Wh + (size_t)row * FH;
    float s1 = 0.f, s2 = 0.f;
#pragma unroll
    for (int v = lane; v < FH; v += 32) {
        float w = wr[v];
        s1 += w * sa[v];
        s2 += w * sa[FH + v];
    }
#pragma unroll
    for (int o = 16; o; o >>= 1) {
        s1 += __shfl_xor_sync(0xffffffffu, s1, o);
        s2 += __shfl_xor_sync(0xffffffffu, s2, o);
    }
    if (lane == 0) { src[row] = s1; dst[row] = s2; }
}

// ---------------- K3: tf32 mma fused attention, cp.async Wh feed -------------
// ROWS x 256 tile, 512 threads, 16 warps (4x4). Wh: 3-buffer cp.async depth-2.
// Loop: wait_group(1) -> sync -> issue cp(kt+2) -> P(kt+1) -> MMA(kt).
#define ATTN_SMEM(R) (2 * (R) * PSROW * 4 + 3 * 32 * WROW * 4 + 512 * 4)

template <int ROWS, int PARTIAL>
__global__ void __launch_bounds__(512, 1)
attn_kernel() {
    constexpr int MT  = ROWS / 64;
    constexpr int PG  = 512 / ROWS;
    constexpr int KPT = 32 / PG;
    extern __shared__ char smem[];
    float* Ps    = (float*)smem;                          // [2][ROWS*PSROW]
    float* Whs   = (float*)(smem + 2 * ROWS * PSROW * 4); // [3][32*WROW]
    float* lpart = (float*)(smem + 2 * ROWS * PSROW * 4 + 3 * 32 * WROW * 4);
    const uint32_t whs_s = (uint32_t)__cvta_generic_to_shared(Whs);

    const int tid = threadIdx.x;
    const int wid = tid >> 5, lane = tid & 31;
    const int wr = wid >> 2, wc = wid & 3;
    const int i0 = blockIdx.x * ROWS;

    const float* Wh; const float* srcT; const float* dR;
    int jbase, NKT;
    if (PARTIAL) {
        Wh = g_Wh2; srcT = g_src2; dR = g_dst2;
        jbase = blockIdx.y * (NV / 2); NKT = (NV / 2) / 32;
    } else {
        const int b = blockIdx.z;
        Wh = g_Wh1 + (size_t)b * NV * FH;
        srcT = g_src1 + b * NV; dR = g_dst1 + b * NV;
        jbase = 0; NKT = NV / 32;
    }

    const int prow  = tid / PG;
    const int kbase = (tid % PG) * KPT;
    const float si  = srcT[i0 + prow];
    const unsigned* adjrow = g_adjbits + (size_t)(i0 + prow) * NW + (jbase >> 5);
    const int jrow = tid >> 4, fbase = (tid & 15) * 4;
    const int ar = lane >> 2, ak = lane & 3;

    // cp.async source/dest for this thread
    const float* wsrc0 = Wh + (size_t)(jbase + jrow) * FH + fbase;
    const uint32_t wdst0 = whs_s + (uint32_t)(jrow * WROW + fbase) * 4u;

    float d[MT][8][4];
#pragma unroll
    for (int mt = 0; mt < MT; mt++)
#pragma unroll
        for (int nt = 0; nt < 8; nt++)
#pragma unroll
            for (int v = 0; v < 4; v++) d[mt][nt][v] = 0.f;
    float lsum = 0.f;

    // P compute lambda-ish macro
#define COMPUTE_P(kt_, pbuf_)                                               \
    {                                                                       \
        const int j0_ = jbase + (kt_) * 32;                                 \
        unsigned aw_ = adjrow[kt_] >> kbase;                                \
        float pv_[KPT];                                                     \
        _Pragma("unroll")                                                   \
        for (int g_ = 0; g_ < KPT / 4; g_++) {                              \
            float4 dv_ = *(const float4*)(dR + j0_ + kbase + 4 * g_);       \
            float dd_[4] = {dv_.x, dv_.y, dv_.z, dv_.w};                    \
            _Pragma("unroll")                                               \
            for (int c_ = 0; c_ < 4; c_++) {                                \
                const int u_ = 4 * g_ + c_;                                 \
                float e_ = si + dd_[c_];                                    \
                e_ = e_ > 0.f ? e_ : 0.2f * e_;                             \
                float p_ = ((aw_ >> u_) & 1u) ? __expf(e_) : 0.f;           \
                p_ = tf32r(p_);                                             \
                lsum += p_;                                                 \
                pv_[u_] = p_;                                               \
            }                                                               \
        }                                                                   \
        float* pb_ = (pbuf_) + prow * PSROW + kbase;                        \
        _Pragma("unroll")                                                   \
        for (int g_ = 0; g_ < KPT / 4; g_++)                                \
            *(float4*)(pb_ + 4 * g_) =                                      \
                make_float4(pv_[4*g_], pv_[4*g_+1], pv_[4*g_+2], pv_[4*g_+3]); \
    }

#define ISSUE_WH(kt_, buf_)                                                 \
    {                                                                       \
        const float* wp_ = wsrc0 + (size_t)(kt_) * 32 * FH;                 \
        const uint32_t wd_ = wdst0 + (uint32_t)(buf_) * 32u * WROW * 4u;    \
        _Pragma("unroll")                                                   \
        for (int q_ = 0; q_ < 4; q_++)                                      \
            cp16(wd_ + q_ * 64u * 4u, wp_ + 64 * q_);                       \
    }

    // ---- prologue ----
    ISSUE_WH(0, 0); cp_commit();
    if (1 < NKT) { ISSUE_WH(1, 1); }
    cp_commit();
    COMPUTE_P(0, Ps);

    for (int kt = 0; kt < NKT; kt++) {
        cp_wait1();          // Wh(kt) complete (per-thread)
        __syncthreads();     // visibility; prev MMA reads done
        if (kt + 2 < NKT) { ISSUE_WH(kt + 2, (kt + 2) % 3); }
        cp_commit();         // empty group at tail keeps accounting exact
        if (kt + 1 < NKT) { COMPUTE_P(kt + 1, Ps + ((kt + 1) & 1) * ROWS * PSROW); }

        const float* pB = Ps + (kt & 1) * ROWS * PSROW;
        const float* wB = Whs + (kt % 3) * 32 * WROW;
#pragma unroll
        for (int kk = 0; kk < 4; kk++) {
            const int k0 = kk * 8;
            uint32_t a[MT][4];
#pragma unroll
            for (int mt = 0; mt < MT; mt++) {
                const float* pr = pB + (wr * 16 * MT + mt * 16 + ar) * PSROW + k0 + ak;
                a[mt][0] = __float_as_uint(pr[0]);
                a[mt][1] = __float_as_uint(pr[8 * PSROW]);
                a[mt][2] = __float_as_uint(pr[4]);
                a[mt][3] = __float_as_uint(pr[8 * PSROW + 4]);
            }
#pragma unroll
            for (int nt = 0; nt < 8; nt++) {
                const int n = wc * 64 + nt * 8 + ar;
                uint32_t b0 = __float_as_uint(wB[(k0 + ak) * WROW + n]);
                uint32_t b1 = __float_as_uint(wB[(k0 + ak + 4) * WROW + n]);
#pragma unroll
                for (int mt = 0; mt < MT; mt++)
                    mma_tf32(d[mt][nt], a[mt], b0, b1);
            }
        }
    }
    __syncthreads();
    lpart[tid] = lsum;       // lpart[prow*PG + sub]
    __syncthreads();

    if (PARTIAL) {
        float* np = g_np + (size_t)blockIdx.y * NV * FO;
#pragma unroll
        for (int mt = 0; mt < MT; mt++) {
            const int r0 = wr * 16 * MT + mt * 16 + ar;
            const int r1 = r0 + 8;
#pragma unroll
            for (int nt = 0; nt < 8; nt++) {
                const int c = wc * 64 + nt * 8 + 2 * ak;
                *(float2*)(np + (size_t)(i0 + r0) * FO + c) = make_float2(d[mt][nt][0], d[mt][nt][1]);
                *(float2*)(np + (size_t)(i0 + r1) * FO + c) = make_float2(d[mt][nt][2], d[mt][nt][3]);
            }
        }
        if (tid < ROWS) {
            float l = 0.f;
#pragma unroll
            for (int g = 0; g < PG; g++) l += lpart[tid * PG + g];
            g_lp[blockIdx.y * NV + i0 + tid] = l;
        }
    } else {
        float* out = g_h1;
        const int coloff = blockIdx.z * FH;
#pragma unroll
        for (int mt = 0; mt < MT; mt++) {
            const int r0 = wr * 16 * MT + mt * 16 + ar;
            const int r1 = r0 + 8;
            float l0 = 0.f, l1 = 0.f;
#pragma unroll
            for (int g = 0; g < PG; g++) {
                l0 += lpart[r0 * PG + g];
                l1 += lpart[r1 * PG + g];
            }
            const float rl0 = 1.0f / l0, rl1 = 1.0f / l1;
#pragma unroll
            for (int nt = 0; nt < 8; nt++) {
                const int c = coloff + wc * 64 + nt * 8 + 2 * ak;
                float o0 = d[mt][nt][0] * rl0, o1 = d[mt][nt][1] * rl0;
                float o2 = d[mt][nt][2] * rl1, o3 = d[mt][nt][3] * rl1;
                o0 = o0 > 0.f ? o0 : (__expf(o0) - 1.0f);
                o1 = o1 > 0.f ? o1 : (__expf(o1) - 1.0f);
                o2 = o2 > 0.f ? o2 : (__expf(o2) - 1.0f);
                o3 = o3 > 0.f ? o3 : (__expf(o3) - 1.0f);
                *(float2*)(out + (size_t)(i0 + r0) * F2 + c) = make_float2(o0, o1);
                *(float2*)(out + (size_t)(i0 + r1) * F2 + c) = make_float2(o2, o3);
            }
        }
    }
#undef COMPUTE_P
#undef ISSUE_WH
}

// ---------------- K4: combine split partials (layer 1 epilogue) --------------
__global__ void combine_kernel(float* __restrict__ out) {
    const int i = blockIdx.x;
    const int c = threadIdx.x;
    const float l = g_lp[i] + g_lp[NV + i];
    const float n = g_np[(size_t)i * FO + c] +
                    g_np[(size_t)NV * FO + (size_t)i * FO + c];
    out[(size_t)i * FO + c] = n / l;
}

// ---------------- launch -----------------------------------------------------
extern "C" void kernel_launch(void* const* d_in, const int* in_sizes, int n_in,
                              void* d_out, int out_size) {
    (void)in_sizes; (void)n_in; (void)out_size;
    const float* x   = (const float*)d_in[0];
    const int*   adj = (const int*)d_in[1];
    const float* W1  = (const float*)d_in[2];
    const float* a1  = (const float*)d_in[3];
    const float* W2  = (const float*)d_in[4];
    const float* a2  = (const float*)d_in[5];
    float* out = (float*)d_out;

    static int inited = 0;
    if (!inited) {
        cudaFuncSetAttribute(gemm_tf32_kernel<128>,
            cudaFuncAttributeMaxDynamicSharedMemorySize, GEMM_SMEM(128));
        cudaFuncSetAttribute(gemm_tf32_kernel<64>,
            cudaFuncAttributeMaxDynamicSharedMemorySize, GEMM_SMEM(64));
        cudaFuncSetAttribute(attn_kernel<128, 0>,
            cudaFuncAttributeMaxDynamicSharedMemorySize, ATTN_SMEM(128));
        cudaFuncSetAttribute(attn_kernel<64, 1>,
            cudaFuncAttributeMaxDynamicSharedMemorySize, ATTN_SMEM(64));
        inited = 1;
    }

    float* Wh1p; cudaGetSymbolAddress((void**)&Wh1p, g_Wh1);
    float* h1p;  cudaGetSymbolAddress((void**)&h1p,  g_h1);
    float* Wh2p; cudaGetSymbolAddress((void**)&Wh2p, g_Wh2);

    adjbits_kernel<<<(NV * NV) / 256, 256>>>(adj);
    gemm_tf32_kernel<128><<<dim3(NV / 128, NHEADS), 512, GEMM_SMEM(128)>>>(
        x, W1, Wh1p, F1, (long)F1 * FH, (long)NV * FH);
    srcdst_kernel<<<dim3(NV / 8, NHEADS), 256>>>(a1, 0);
    attn_kernel<128, 0><<<dim3(NV / 128, 1, NHEADS), 512, ATTN_SMEM(128)>>>();
    gemm_tf32_kernel<64><<<dim3(NV / 64, 1), 512, GEMM_SMEM(64)>>>(
        h1p, W2, Wh2p, F2, 0L, 0L);
    srcdst_kernel<<<dim3(NV / 8, 1), 256>>>(a2, 1);
    attn_kernel<64, 1><<<dim3(NV / 64, 2), 512, ATTN_SMEM(64)>>>();
    combine_kernel<<<NV, 256>>>(out);
}

// round 8
// speedup vs baseline: 1.8593x; 1.0868x over previous
#include <cuda_runtime.h>
#include <cstdint>

#define NV 4096
#define F1 512
#define FH 256
#define NHEADS 4
#define F2 1024   // nhid * nheads
#define FO 256
#define NW (NV/32) // 128 bitmask words per row

#define PSROW 36   // scalar P/A tile row stride: conflict-free 32-bit A frags
#define WROW  264  // Wh/B tile row stride: 264%32==8 -> conflict-free B frags

// ---------------- scratch (static device memory; no allocations) ------------
__device__ __align__(16) float  g_Wh1[NHEADS * NV * FH]; // tf32-rounded
__device__ __align__(16) float  g_h1[NV * F2];
__device__ __align__(16) float  g_Wh2[NV * FO];          // tf32-rounded
__device__ __align__(16) float  g_src1[NHEADS * NV];
__device__ __align__(16) float  g_dst1[NHEADS * NV];
__device__ __align__(16) float  g_src2[NV];
__device__ __align__(16) float  g_dst2[NV];
__device__ __align__(16) float  g_np[2 * NV * FO];       // L1 split numerators
__device__ __align__(16) float  g_lp[2 * NV];            // L1 split denominators
__device__ __align__(16) unsigned g_adjbits[NV * NW];    // 2 MB

// ---------------- tf32 mma / cp.async helpers --------------------------------
__device__ __forceinline__ float tf32r(float x) {
    uint32_t u;
    asm("cvt.rna.tf32.f32 %0, %1;" : "=r"(u) : "f"(x));
    return __uint_as_float(u);
}
__device__ __forceinline__ void mma_tf32(float* d, const uint32_t* a,
                                         uint32_t b0, uint32_t b1) {
    asm volatile(
        "mma.sync.aligned.m16n8k8.row.col.f32.tf32.tf32.f32 "
        "{%0,%1,%2,%3}, {%4,%5,%6,%7}, {%8,%9}, {%0,%1,%2,%3};"
        : "+f"(d[0]), "+f"(d[1]), "+f"(d[2]), "+f"(d[3])
        : "r"(a[0]), "r"(a[1]), "r"(a[2]), "r"(a[3]), "r"(b0), "r"(b1));
}
__device__ __forceinline__ void cp16(uint32_t saddr, const void* gptr) {
    asm volatile("cp.async.cg.shared.global [%0], [%1], 16;"
                 :: "r"(saddr), "l"(gptr));
}
__device__ __forceinline__ void cp_commit() {
    asm volatile("cp.async.commit_group;");
}
__device__ __forceinline__ void cp_wait1() {
    asm volatile("cp.async.wait_group 1;");
}

// ---------------- K0: adjacency -> bitmask ----------------------------------
__global__ void adjbits_kernel(const int* __restrict__ adj) {
    int idx = blockIdx.x * blockDim.x + threadIdx.x;   // over NV*NV
    unsigned bit = (adj[idx] != 0) ? 1u : 0u;
    unsigned w = __ballot_sync(0xffffffffu, bit);
    if ((threadIdx.x & 31) == 0) g_adjbits[idx >> 5] = w;
}

// ---------------- K1: tf32 mma GEMM  C[*,256] = A[*,K] @ B[K,256] ------------
// C is stored tf32-rounded (consumed by attn tensor path; negligible error).
template <int ROWS>
__global__ void __launch_bounds__(512, 1)
gemm_tf32_kernel(const float* __restrict__ A, const float* __restrict__ B,
                 float* __restrict__ C, int K, long bStride, long cStride) {
    constexpr int MT = ROWS / 64;
    constexpr int TPR = 512 / ROWS;     // threads per A-row
    constexpr int AK  = 32 / TPR;       // A cols per thread
    extern __shared__ char smem[];
    float* As = (float*)smem;                            // [2][ROWS*PSROW]
    float* Bs = (float*)(smem + 2 * ROWS * PSROW * 4);   // [2][32*WROW]

    const int tid = threadIdx.x;
    const int wid = tid >> 5, lane = tid & 31;
    const int wr = wid >> 2, wc = wid & 3;
    const float* Bb = B + (size_t)blockIdx.y * bStride;
    float* Cb = C + (size_t)blockIdx.y * cStride;
    const int i0 = blockIdx.x * ROWS;

    const int arow = tid / TPR, ak0 = (tid % TPR) * AK;
    const int jrow = tid >> 4, fbase = (tid & 15) * 4;
    const int ar = lane >> 2, ak = lane & 3;

    float d[MT][8][4];
#pragma unroll
    for (int mt = 0; mt < MT; mt++)
#pragma unroll
        for (int nt = 0; nt < 8; nt++)
#pragma unroll
            for (int v = 0; v < 4; v++) d[mt][nt][v] = 0.f;

    const int NKT = K / 32;
    for (int kt = 0; kt < NKT; kt++) {
        const int bb = kt & 1;
        const int k0g = kt * 32;
        {
            const float* wp = Bb + (size_t)(k0g + jrow) * FH + fbase;
            float* bs = Bs + bb * 32 * WROW + jrow * WROW + fbase;
#pragma unroll
            for (int q = 0; q < 4; q++) {
                float4 v = *(const float4*)(wp + 64 * q);
                *(float4*)(bs + 64 * q) =
                    make_float4(tf32r(v.x), tf32r(v.y), tf32r(v.z), tf32r(v.w));
            }
            const float* ap = A + (size_t)(i0 + arow) * K + k0g + ak0;
            float* as = As + bb * ROWS * PSROW + arow * PSROW + ak0;
#pragma unroll
            for (int q = 0; q < AK / 4; q++) {
                float4 v = *(const float4*)(ap + 4 * q);
                *(float4*)(as + 4 * q) =
                    make_float4(tf32r(v.x), tf32r(v.y), tf32r(v.z), tf32r(v.w));
            }
        }
        __syncthreads();
        const float* pB = As + bb * ROWS * PSROW;
        const float* wB = Bs + bb * 32 * WROW;
#pragma unroll
        for (int kk = 0; kk < 4; kk++) {
            const int k0 = kk * 8;
            uint32_t a[MT][4];
#pragma unroll
            for (int mt = 0; mt < MT; mt++) {
                const float* pr = pB + (wr * 16 * MT + mt * 16 + ar) * PSROW + k0 + ak;
                a[mt][0] = __float_as_uint(pr[0]);
                a[mt][1] = __float_as_uint(pr[8 * PSROW]);
                a[mt][2] = __float_as_uint(pr[4]);
                a[mt][3] = __float_as_uint(pr[8 * PSROW + 4]);
            }
#pragma unroll
            for (int nt = 0; nt < 8; nt++) {
                const int n = wc * 64 + nt * 8 + ar;
                uint32_t b0 = __float_as_uint(wB[(k0 + ak) * WROW + n]);
                uint32_t b1 = __float_as_uint(wB[(k0 + ak + 4) * WROW + n]);
#pragma unroll
                for (int mt = 0; mt < MT; mt++)
                    mma_tf32(d[mt][nt], a[mt], b0, b1);
            }
        }
        __syncthreads();
    }
#pragma unroll
    for (int mt = 0; mt < MT; mt++) {
        const int r0 = wr * 16 * MT + mt * 16 + ar;
        const int r1 = r0 + 8;
#pragma unroll
        for (int nt = 0; nt < 8; nt++) {
            const int c = wc * 64 + nt * 8 + 2 * ak;
            *(float2*)(Cb + (size_t)(i0 + r0) * FH + c) =
                make_float2(tf32r(d[mt][nt][0]), tf32r(d[mt][nt][1]));
            *(float2*)(Cb + (size_t)(i0 + r1) * FH + c) =
                make_float2(tf32r(d[mt][nt][2]), tf32r(d[mt][nt][3]));
        }
    }
}

#define GEMM_SMEM(R) (2 * (R) * PSROW * 4 + 2 * 32 * WROW * 4)

// ---------------- K2: src/dst projections (exact fp32) -----------------------
__global__ void srcdst_kernel(const float* __restrict__ avec, int layer) {
    __shared__ float sa[2 * FH];
    const int b = blockIdx.y;
    const float* Wh = layer ? g_Wh2 : g_Wh1 + (size_t)b * NV * FH;
    const float* a  = avec + b * 2 * FH;
    float* src = layer ? g_src2 : g_src1 + b * NV;
    float* dst = layer ? g_dst2 : g_dst1 + b * NV;

    const int tid = threadIdx.x;
    for (int i = tid; i < 2 * FH; i += blockDim.x) sa[i] = a[i];
    __syncthreads();

    const int warp = tid >> 5, lane = tid & 31;
    const int row = blockIdx.x * 8 + warp;
    const float* wr = Wh + (size_t)row * FH;
    float s1 = 0.f, s2 = 0.f;
#pragma unroll
    for (int v = lane; v < FH; v += 32) {
        float w = wr[v];
        s1 += w * sa[v];
        s2 += w * sa[FH + v];
    }
#pragma unroll
    for (int o = 16; o; o >>= 1) {
        s1 += __shfl_xor_sync(0xffffffffu, s1, o);
        s2 += __shfl_xor_sync(0xffffffffu, s2, o);
    }
    if (lane == 0) { src[row] = s1; dst[row] = s2; }
}

// ---------------- K3: tf32 mma fused attention, cp.async + staggered ---------
// ROWS x 256 tile, 512 threads, 16 warps (4x4). Wh: 3-buffer cp.async depth-2.
// Per-SMSP half the warps run MMA-first, half P-first (phase stagger).
// ROWS=128 (PG=4): pair-packed P tile (stride 40) -> LDS.64 A frags.
#define PST_OF(R) ((R) == 128 ? 40 : 36)
#define ATTN_SMEM(R) (2 * (R) * PST_OF(R) * 4 + 3 * 32 * WROW * 4 + 512 * 4)

template <int ROWS, int PARTIAL>
__global__ void __launch_bounds__(512, 1)
attn_kernel() {
    constexpr int MT  = ROWS / 64;
    constexpr int PG  = 512 / ROWS;
    constexpr int KPT = 32 / PG;
    constexpr int PST = PST_OF(ROWS);
    extern __shared__ char smem[];
    float* Ps    = (float*)smem;                          // [2][ROWS*PST]
    float* Whs   = (float*)(smem + 2 * ROWS * PST * 4);   // [3][32*WROW]
    float* lpart = (float*)(smem + 2 * ROWS * PST * 4 + 3 * 32 * WROW * 4);
    const uint32_t whs_s = (uint32_t)__cvta_generic_to_shared(Whs);

    const int tid = threadIdx.x;
    const int wid = tid >> 5, lane = tid & 31;
    const int wr = wid >> 2, wc = wid & 3;
    const int i0 = blockIdx.x * ROWS;
    const bool mmaFirst = ((wid >> 2) & 1) != 0;   // per-SMSP 2/2 split

    const float* Wh; const float* srcT; const float* dR;
    int jbase, NKT;
    if (PARTIAL) {
        Wh = g_Wh2; srcT = g_src2; dR = g_dst2;
        jbase = blockIdx.y * (NV / 2); NKT = (NV / 2) / 32;
    } else {
        const int b = blockIdx.z;
        Wh = g_Wh1 + (size_t)b * NV * FH;
        srcT = g_src1 + b * NV; dR = g_dst1 + b * NV;
        jbase = 0; NKT = NV / 32;
    }

    const int prow  = tid / PG;
    const int kbase = (tid % PG) * KPT;
    const float si  = srcT[i0 + prow];
    const unsigned* adjrow = g_adjbits + (size_t)(i0 + prow) * NW + (jbase >> 5);
    const int jrow = tid >> 4, fbase = (tid & 15) * 4;
    const int ar = lane >> 2, ak = lane & 3;

    const float* wsrc0 = Wh + (size_t)(jbase + jrow) * FH + fbase;
    const uint32_t wdst0 = whs_s + (uint32_t)(jrow * WROW + fbase) * 4u;

    float d[MT][8][4];
#pragma unroll
    for (int mt = 0; mt < MT; mt++)
#pragma unroll
        for (int nt = 0; nt < 8; nt++)
#pragma unroll
            for (int v = 0; v < 4; v++) d[mt][nt][v] = 0.f;
    float lsum = 0.f;

#define COMPUTE_P(kt_, pbuf_)                                               \
    {                                                                       \
        const int j0_ = jbase + (kt_) * 32;                                 \
        unsigned aw_ = adjrow[kt_] >> kbase;                                \
        float pv_[KPT];                                                     \
        _Pragma("unroll")                                                   \
        for (int g_ = 0; g_ < KPT / 4; g_++) {                              \
            float4 dv_ = *(const float4*)(dR + j0_ + kbase + 4 * g_);       \
            float dd_[4] = {dv_.x, dv_.y, dv_.z, dv_.w};                    \
            _Pragma("unroll")                                               \
            for (int c_ = 0; c_ < 4; c_++) {                                \
                const int u_ = 4 * g_ + c_;                                 \
                float e_ = si + dd_[c_];                                    \
                e_ = e_ > 0.f ? e_ : 0.2f * e_;                             \
                float p_ = ((aw_ >> u_) & 1u) ? __expf(e_) : 0.f;           \
                p_ = tf32r(p_);                                             \
                lsum += p_;                                                 \
                pv_[u_] = p_;                                               \
            }                                                               \
        }                                                                   \
        if constexpr (PG == 4) {                                            \
            float2* pb_ = (float2*)((pbuf_) + prow * PST + kbase);          \
            _Pragma("unroll")                                               \
            for (int c_ = 0; c_ < 4; c_++)                                  \
                pb_[c_] = make_float2(pv_[c_], pv_[c_ + 4]);                \
        } else {                                                            \
            float* pb_ = (pbuf_) + prow * PST + kbase;                      \
            _Pragma("unroll")                                               \
            for (int g_ = 0; g_ < KPT / 4; g_++)                            \
                *(float4*)(pb_ + 4 * g_) = make_float4(                     \
                    pv_[4*g_], pv_[4*g_+1], pv_[4*g_+2], pv_[4*g_+3]);      \
        }                                                                   \
    }

#define ISSUE_WH(kt_, buf_)                                                 \
    {                                                                       \
        const float* wp_ = wsrc0 + (size_t)(kt_) * 32 * FH;                 \
        const uint32_t wd_ = wdst0 + (uint32_t)(buf_) * 32u * WROW * 4u;    \
        _Pragma("unroll")                                                   \
        for (int q_ = 0; q_ < 4; q_++)                                      \
            cp16(wd_ + q_ * 64u * 4u, wp_ + 64 * q_);                       \
    }

#define PREP_STEP(kt_)                                                      \
    {                                                                       \
        if ((kt_) + 2 < NKT) { ISSUE_WH((kt_) + 2, ((kt_) + 2) % 3); }      \
        cp_commit();                                                        \
        if ((kt_) + 1 < NKT) {                                              \
            COMPUTE_P((kt_) + 1, Ps + (((kt_) + 1) & 1) * ROWS * PST);      \
        }                                                                   \
    }

#define MMA_STEP(kt_)                                                       \
    {                                                                       \
        const float* pB = Ps + ((kt_) & 1) * ROWS * PST;                    \
        const float* wB = Whs + ((kt_) % 3) * 32 * WROW;                    \
        _Pragma("unroll")                                                   \
        for (int kk = 0; kk < 4; kk++) {                                    \
            const int k0 = kk * 8;                                          \
            uint32_t a[MT][4];                                              \
            _Pragma("unroll")                                               \
            for (int mt = 0; mt < MT; mt++) {                               \
                const int row_ = wr * 16 * MT + mt * 16 + ar;               \
                if constexpr (PG == 4) {                                    \
                    const float* pr = pB + row_ * PST + k0 + 2 * ak;        \
                    float2 q0 = *(const float2*)pr;                         \
                    float2 q1 = *(const float2*)(pr + 8 * PST);             \
                    a[mt][0] = __float_as_uint(q0.x);                       \
                    a[mt][1] = __float_as_uint(q1.x);                       \
                    a[mt][2] = __float_as_uint(q0.y);                       \
                    a[mt][3] = __float_as_uint(q1.y);                       \
                } else {                                                    \
                    const float* pr = pB + row_ * PST + k0 + ak;            \
                    a[mt][0] = __float_as_uint(pr[0]);                      \
                    a[mt][1] = __float_as_uint(pr[8 * PST]);                \
                    a[mt][2] = __float_as_uint(pr[4]);                      \
                    a[mt][3] = __float_as_uint(pr[8 * PST + 4]);            \
                }                                                           \
            }                                                               \
            _Pragma("unroll")                                               \
            for (int nt = 0; nt < 8; nt++) {                                \
                const int n = wc * 64 + nt * 8 + ar;                        \
                uint32_t b0 = __float_as_uint(wB[(k0 + ak) * WROW + n]);    \
                uint32_t b1 = __float_as_uint(wB[(k0 + ak + 4) * WROW + n]);\
                _Pragma("unroll")                                           \
                for (int mt = 0; mt < MT; mt++)                             \
                    mma_tf32(d[mt][nt], a[mt], b0, b1);                     \
            }                                                               \
        }                                                                   \
    }

    // ---- prologue ----
    ISSUE_WH(0, 0); cp_commit();
    if (1 < NKT) { ISSUE_WH(1, 1); }
    cp_commit();
    COMPUTE_P(0, Ps);

    for (int kt = 0; kt < NKT; kt++) {
        cp_wait1();          // Wh(kt) complete (per-thread)
        __syncthreads();     // visibility; prev MMA reads done
        if (mmaFirst) {
            MMA_STEP(kt);
            PREP_STEP(kt);
        } else {
            PREP_STEP(kt);
            MMA_STEP(kt);
        }
    }
    __syncthreads();
    lpart[tid] = lsum;       // lpart[prow*PG + sub]
    __syncthreads();

    if (PARTIAL) {
        float* np = g_np + (size_t)blockIdx.y * NV * FO;
#pragma unroll
        for (int mt = 0; mt < MT; mt++) {
            const int r0 = wr * 16 * MT + mt * 16 + ar;
            const int r1 = r0 + 8;
#pragma unroll
            for (int nt = 0; nt < 8; nt++) {
                const int c = wc * 64 + nt * 8 + 2 * ak;
                *(float2*)(np + (size_t)(i0 + r0) * FO + c) = make_float2(d[mt][nt][0], d[mt][nt][1]);
                *(float2*)(np + (size_t)(i0 + r1) * FO + c) = make_float2(d[mt][nt][2], d[mt][nt][3]);
            }
        }
        if (tid < ROWS) {
            float l = 0.f;
#pragma unroll
            for (int g = 0; g < PG; g++) l += lpart[tid * PG + g];
            g_lp[blockIdx.y * NV + i0 + tid] = l;
        }
    } else {
        float* out = g_h1;
        const int coloff = blockIdx.z * FH;
#pragma unroll
        for (int mt = 0; mt < MT; mt++) {
            const int r0 = wr * 16 * MT + mt * 16 + ar;
            const int r1 = r0 + 8;
            float l0 = 0.f, l1 = 0.f;
#pragma unroll
            for (int g = 0; g < PG; g++) {
                l0 += lpart[r0 * PG + g];
                l1 += lpart[r1 * PG + g];
            }
            const float rl0 = 1.0f / l0, rl1 = 1.0f / l1;
#pragma unroll
            for (int nt = 0; nt < 8; nt++) {
                const int c = coloff + wc * 64 + nt * 8 + 2 * ak;
                float o0 = d[mt][nt][0] * rl0, o1 = d[mt][nt][1] * rl0;
                float o2 = d[mt][nt][2] * rl1, o3 = d[mt][nt][3] * rl1;
                o0 = o0 > 0.f ? o0 : (__expf(o0) - 1.0f);
                o1 = o1 > 0.f ? o1 : (__expf(o1) - 1.0f);
                o2 = o2 > 0.f ? o2 : (__expf(o2) - 1.0f);
                o3 = o3 > 0.f ? o3 : (__expf(o3) - 1.0f);
                *(float2*)(out + (size_t)(i0 + r0) * F2 + c) = make_float2(o0, o1);
                *(float2*)(out + (size_t)(i0 + r1) * F2 + c) = make_float2(o2, o3);
            }
        }
    }
#undef COMPUTE_P
#undef ISSUE_WH
#undef PREP_STEP
#undef MMA_STEP
}

// ---------------- K4: combine split partials (layer 1 epilogue) --------------
__global__ void combine_kernel(float* __restrict__ out) {
    const int i = blockIdx.x;
    const int c = threadIdx.x;
    const float l = g_lp[i] + g_lp[NV + i];
    const float n = g_np[(size_t)i * FO + c] +
                    g_np[(size_t)NV * FO + (size_t)i * FO + c];
    out[(size_t)i * FO + c] = n / l;
}

// ---------------- launch -----------------------------------------------------
extern "C" void kernel_launch(void* const* d_in, const int* in_sizes, int n_in,
                              void* d_out, int out_size) {
    (void)in_sizes; (void)n_in; (void)out_size;
    const float* x   = (const float*)d_in[0];
    const int*   adj = (const int*)d_in[1];
    const float* W1  = (const float*)d_in[2];
    const float* a1  = (const float*)d_in[3];
    const float* W2  = (const float*)d_in[4];
    const float* a2  = (const float*)d_in[5];
    float* out = (float*)d_out;

    static int inited = 0;
    if (!inited) {
        cudaFuncSetAttribute(gemm_tf32_kernel<128>,
            cudaFuncAttributeMaxDynamicSharedMemorySize, GEMM_SMEM(128));
        cudaFuncSetAttribute(gemm_tf32_kernel<64>,
            cudaFuncAttributeMaxDynamicSharedMemorySize, GEMM_SMEM(64));
        cudaFuncSetAttribute(attn_kernel<128, 0>,
            cudaFuncAttributeMaxDynamicSharedMemorySize, ATTN_SMEM(128));
        cudaFuncSetAttribute(attn_kernel<64, 1>,
            cudaFuncAttributeMaxDynamicSharedMemorySize, ATTN_SMEM(64));
        inited = 1;
    }

    float* Wh1p; cudaGetSymbolAddress((void**)&Wh1p, g_Wh1);
    float* h1p;  cudaGetSymbolAddress((void**)&h1p,  g_h1);
    float* Wh2p; cudaGetSymbolAddress((void**)&Wh2p, g_Wh2);

    adjbits_kernel<<<(NV * NV) / 256, 256>>>(adj);
    gemm_tf32_kernel<128><<<dim3(NV / 128, NHEADS), 512, GEMM_SMEM(128)>>>(
        x, W1, Wh1p, F1, (long)F1 * FH, (long)NV * FH);
    srcdst_kernel<<<dim3(NV / 8, NHEADS), 256>>>(a1, 0);
    attn_kernel<128, 0><<<dim3(NV / 128, 1, NHEADS), 512, ATTN_SMEM(128)>>>();
    gemm_tf32_kernel<64><<<dim3(NV / 64, 1), 512, GEMM_SMEM(64)>>>(
        h1p, W2, Wh2p, F2, 0L, 0L);
    srcdst_kernel<<<dim3(NV / 8, 1), 256>>>(a2, 1);
    attn_kernel<64, 1><<<dim3(NV / 64, 2), 512, ATTN_SMEM(64)>>>();
    combine_kernel<<<NV, 256>>>(out);
}

// round 9
// speedup vs baseline: 1.8618x; 1.0014x over previous
#include <cuda_runtime.h>
#include <cstdint>

#define NV 4096
#define F1 512
#define FH 256
#define NHEADS 4
#define F2 1024   // nhid * nheads
#define FO 256
#define NW (NV/32) // 128 bitmask words per row

#define PSROW 36   // scalar P/A tile row stride: conflict-free 32-bit A frags
#define WROW  264  // gemm B tile row stride: 264%32==8 -> conflict-free B frags
#define WR2P  520  // packed Wh tile row stride (floats): 520%32==8 -> LDS.64 conflict-free

// ---------------- scratch (static device memory; no allocations) ------------
__device__ __align__(16) float  g_Wh1[NHEADS * NV * FH];  // row-major (srcdst)
__device__ __align__(16) float  g_Wh1P[NHEADS * NV * FH]; // pair-packed (attn B)
__device__ __align__(16) float  g_h1[NV * F2];
__device__ __align__(16) float  g_Wh2[NV * FO];
__device__ __align__(16) float  g_Wh2P[NV * FO];
__device__ __align__(16) float  g_src1[NHEADS * NV];
__device__ __align__(16) float  g_dst1[NHEADS * NV];
__device__ __align__(16) float  g_src2[NV];
__device__ __align__(16) float  g_dst2[NV];
__device__ __align__(16) float  g_np[2 * NV * FO];       // L1 split numerators
__device__ __align__(16) float  g_lp[2 * NV];            // L1 split denominators
__device__ __align__(16) unsigned g_adjbits[NV * NW];    // 2 MB

// ---------------- tf32 mma / cp.async helpers --------------------------------
__device__ __forceinline__ float tf32r(float x) {
    uint32_t u;
    asm("cvt.rna.tf32.f32 %0, %1;" : "=r"(u) : "f"(x));
    return __uint_as_float(u);
}
__device__ __forceinline__ void mma_tf32(float* d, const uint32_t* a,
                                         uint32_t b0, uint32_t b1) {
    asm volatile(
        "mma.sync.aligned.m16n8k8.row.col.f32.tf32.tf32.f32 "
        "{%0,%1,%2,%3}, {%4,%5,%6,%7}, {%8,%9}, {%0,%1,%2,%3};"
        : "+f"(d[0]), "+f"(d[1]), "+f"(d[2]), "+f"(d[3])
        : "r"(a[0]), "r"(a[1]), "r"(a[2]), "r"(a[3]), "r"(b0), "r"(b1));
}
__device__ __forceinline__ void cp16(uint32_t saddr, const void* gptr) {
    asm volatile("cp.async.cg.shared.global [%0], [%1], 16;"
                 :: "r"(saddr), "l"(gptr));
}
__device__ __forceinline__ void cp_commit() {
    asm volatile("cp.async.commit_group;");
}
__device__ __forceinline__ void cp_wait1() {
    asm volatile("cp.async.wait_group 1;");
}

// ---------------- K0: adjacency -> bitmask ----------------------------------
__global__ void adjbits_kernel(const int* __restrict__ adj) {
    int idx = blockIdx.x * blockDim.x + threadIdx.x;   // over NV*NV
    unsigned bit = (adj[idx] != 0) ? 1u : 0u;
    unsigned w = __ballot_sync(0xffffffffu, bit);
    if ((threadIdx.x & 31) == 0) g_adjbits[idx >> 5] = w;
}

// ---------------- K1: tf32 mma GEMM  C[*,256] = A[*,K] @ B[K,256] ------------
// Writes C row-major (tf32-rounded) AND pair-packed Cp for the attn B feed.
template <int ROWS>
__global__ void __launch_bounds__(512, 1)
gemm_tf32_kernel(const float* __restrict__ A, const float* __restrict__ B,
                 float* __restrict__ C, float* __restrict__ Cp,
                 int K, long bStride, long cStride) {
    constexpr int MT = ROWS / 64;
    constexpr int TPR = 512 / ROWS;     // threads per A-row
    constexpr int AK  = 32 / TPR;       // A cols per thread
    extern __shared__ char smem[];
    float* As = (float*)smem;                            // [2][ROWS*PSROW]
    float* Bs = (float*)(smem + 2 * ROWS * PSROW * 4);   // [2][32*WROW]

    const int tid = threadIdx.x;
    const int wid = tid >> 5, lane = tid & 31;
    const int wr = wid >> 2, wc = wid & 3;
    const float* Bb = B + (size_t)blockIdx.y * bStride;
    float* Cb  = C  + (size_t)blockIdx.y * cStride;
    float* Cpb = Cp + (size_t)blockIdx.y * cStride;
    const int i0 = blockIdx.x * ROWS;

    const int arow = tid / TPR, ak0 = (tid % TPR) * AK;
    const int jrow = tid >> 4, fbase = (tid & 15) * 4;
    const int ar = lane >> 2, ak = lane & 3;

    float d[MT][8][4];
#pragma unroll
    for (int mt = 0; mt < MT; mt++)
#pragma unroll
        for (int nt = 0; nt < 8; nt++)
#pragma unroll
            for (int v = 0; v < 4; v++) d[mt][nt][v] = 0.f;

    const int NKT = K / 32;
    for (int kt = 0; kt < NKT; kt++) {
        const int bb = kt & 1;
        const int k0g = kt * 32;
        {
            const float* wp = Bb + (size_t)(k0g + jrow) * FH + fbase;
            float* bs = Bs + bb * 32 * WROW + jrow * WROW + fbase;
#pragma unroll
            for (int q = 0; q < 4; q++) {
                float4 v = *(const float4*)(wp + 64 * q);
                *(float4*)(bs + 64 * q) =
                    make_float4(tf32r(v.x), tf32r(v.y), tf32r(v.z), tf32r(v.w));
            }
            const float* ap = A + (size_t)(i0 + arow) * K + k0g + ak0;
            float* as = As + bb * ROWS * PSROW + arow * PSROW + ak0;
#pragma unroll
            for (int q = 0; q < AK / 4; q++) {
                float4 v = *(const float4*)(ap + 4 * q);
                *(float4*)(as + 4 * q) =
                    make_float4(tf32r(v.x), tf32r(v.y), tf32r(v.z), tf32r(v.w));
            }
        }
        __syncthreads();
        const float* pB = As + bb * ROWS * PSROW;
        const float* wB = Bs + bb * 32 * WROW;
#pragma unroll
        for (int kk = 0; kk < 4; kk++) {
            const int k0 = kk * 8;
            uint32_t a[MT][4];
#pragma unroll
            for (int mt = 0; mt < MT; mt++) {
                const float* pr = pB + (wr * 16 * MT + mt * 16 + ar) * PSROW + k0 + ak;
                a[mt][0] = __float_as_uint(pr[0]);
                a[mt][1] = __float_as_uint(pr[8 * PSROW]);
                a[mt][2] = __float_as_uint(pr[4]);
                a[mt][3] = __float_as_uint(pr[8 * PSROW + 4]);
            }
#pragma unroll
            for (int nt = 0; nt < 8; nt++) {
                const int n = wc * 64 + nt * 8 + ar;
                uint32_t b0 = __float_as_uint(wB[(k0 + ak) * WROW + n]);
                uint32_t b1 = __float_as_uint(wB[(k0 + ak + 4) * WROW + n]);
#pragma unroll
                for (int mt = 0; mt < MT; mt++)
                    mma_tf32(d[mt][nt], a[mt], b0, b1);
            }
        }
        __syncthreads();
    }
#pragma unroll
    for (int mt = 0; mt < MT; mt++) {
        const int r0 = wr * 16 * MT + mt * 16 + ar;
        const int r1 = r0 + 8;
        const int R0 = i0 + r0, R1 = i0 + r1;
        // packed row bases: blk*32*FH + g*2*FH + h, g=((jj>>3)*4+(jj&3)), h=(jj>>2)&1
        float* p0 = Cpb + (size_t)(R0 >> 5) * 32 * FH +
                    ((((R0 & 31) >> 3) * 4 + (R0 & 3)) * 2) * FH + ((R0 >> 2) & 1);
        float* p1 = Cpb + (size_t)(R1 >> 5) * 32 * FH +
                    ((((R1 & 31) >> 3) * 4 + (R1 & 3)) * 2) * FH + ((R1 >> 2) & 1);
#pragma unroll
        for (int nt = 0; nt < 8; nt++) {
            const int c = wc * 64 + nt * 8 + 2 * ak;
            float t0 = tf32r(d[mt][nt][0]), t1 = tf32r(d[mt][nt][1]);
            float t2 = tf32r(d[mt][nt][2]), t3 = tf32r(d[mt][nt][3]);
            *(float2*)(Cb + (size_t)R0 * FH + c) = make_float2(t0, t1);
            *(float2*)(Cb + (size_t)R1 * FH + c) = make_float2(t2, t3);
            p0[(size_t)c * 2] = t0; p0[(size_t)(c + 1) * 2] = t1;
            p1[(size_t)c * 2] = t2; p1[(size_t)(c + 1) * 2] = t3;
        }
    }
}

#define GEMM_SMEM(R) (2 * (R) * PSROW * 4 + 2 * 32 * WROW * 4)

// ---------------- K2: src/dst projections (exact fp32) -----------------------
__global__ void srcdst_kernel(const float* __restrict__ avec, int layer) {
    __shared__ float sa[2 * FH];
    const int b = blockIdx.y;
    const float* Wh = layer ? g_Wh2 : g_Wh1 + (size_t)b * NV * FH;
    const float* a  = avec + b * 2 * FH;
    float* src = layer ? g_src2 : g_src1 + b * NV;
    float* dst = layer ? g_dst2 : g_dst1 + b * NV;

    const int tid = threadIdx.x;
    for (int i = tid; i < 2 * FH; i += blockDim.x) sa[i] = a[i];
    __syncthreads();

    const int warp = tid >> 5, lane = tid & 31;
    const int row = blockIdx.x * 8 + warp;
    const float* wr = Wh + (size_t)row * FH;
    float s1 = 0.f, s2 = 0.f;
#pragma unroll
    for (int v = lane; v < FH; v += 32) {
        float w = wr[v];
        s1 += w * sa[v];
        s2 += w * sa[FH + v];
    }
#pragma unroll
    for (int o = 16; o; o >>= 1) {
        s1 += __shfl_xor_sync(0xffffffffu, s1, o);
        s2 += __shfl_xor_sync(0xffffffffu, s2, o);
    }
    if (lane == 0) { src[row] = s1; dst[row] = s2; }
}

// ---------------- K3: tf32 mma fused attention -------------------------------
// cp.async packed-Wh feed (3 bufs, depth 2), per-SMSP phase stagger,
// pair-packed P (ROWS=128) and pair-packed Wh -> all frags LDS.64.
#define PST_OF(R) ((R) == 128 ? 40 : 36)
#define ATTN_SMEM(R) (2 * (R) * PST_OF(R) * 4 + 3 * 16 * WR2P * 4 + 512 * 4)

template <int ROWS, int PARTIAL>
__global__ void __launch_bounds__(512, 1)
attn_kernel() {
    constexpr int MT  = ROWS / 64;
    constexpr int PG  = 512 / ROWS;
    constexpr int KPT = 32 / PG;
    constexpr int PST = PST_OF(ROWS);
    extern __shared__ char smem[];
    float* Ps    = (float*)smem;                          // [2][ROWS*PST]
    float* Whs   = (float*)(smem + 2 * ROWS * PST * 4);   // [3][16*WR2P]
    float* lpart = (float*)(smem + 2 * ROWS * PST * 4 + 3 * 16 * WR2P * 4);
    const uint32_t whs_s = (uint32_t)__cvta_generic_to_shared(Whs);

    const int tid = threadIdx.x;
    const int wid = tid >> 5, lane = tid & 31;
    const int wr = wid >> 2, wc = wid & 3;
    const int i0 = blockIdx.x * ROWS;
    const bool mmaFirst = ((wid >> 2) & 1) != 0;   // per-SMSP 2/2 split

    const float* WhP; const float* srcT; const float* dR;
    int jbase, NKT;
    if (PARTIAL) {
        WhP = g_Wh2P; srcT = g_src2; dR = g_dst2;
        jbase = blockIdx.y * (NV / 2); NKT = (NV / 2) / 32;
    } else {
        const int b = blockIdx.z;
        WhP = g_Wh1P + (size_t)b * NV * FH;
        srcT = g_src1 + b * NV; dR = g_dst1 + b * NV;
        jbase = 0; NKT = NV / 32;
    }

    const int prow  = tid / PG;
    const int kbase = (tid % PG) * KPT;
    const float si  = srcT[i0 + prow];
    const unsigned* adjrow = g_adjbits + (size_t)(i0 + prow) * NW + (jbase >> 5);
    const int ar = lane >> 2, ak = lane & 3;

    // packed Wh cp.async mapping: thread -> (g = tid>>5, f0 = (tid&31)*4)
    const float* wsrc0 = WhP + (size_t)(jbase >> 5) * 32 * FH +
                         (tid >> 5) * 512 + (tid & 31) * 4;
    const uint32_t wdst0 = whs_s +
                           (uint32_t)((tid >> 5) * WR2P + (tid & 31) * 4) * 4u;

    float d[MT][8][4];
#pragma unroll
    for (int mt = 0; mt < MT; mt++)
#pragma unroll
        for (int nt = 0; nt < 8; nt++)
#pragma unroll
            for (int v = 0; v < 4; v++) d[mt][nt][v] = 0.f;
    float lsum = 0.f;

#define COMPUTE_P(kt_, pbuf_)                                               \
    {                                                                       \
        const int j0_ = jbase + (kt_) * 32;                                 \
        unsigned aw_ = adjrow[kt_] >> kbase;                                \
        float pv_[KPT];                                                     \
        _Pragma("unroll")                                                   \
        for (int g_ = 0; g_ < KPT / 4; g_++) {                              \
            float4 dv_ = *(const float4*)(dR + j0_ + kbase + 4 * g_);       \
            float dd_[4] = {dv_.x, dv_.y, dv_.z, dv_.w};                    \
            _Pragma("unroll")                                               \
            for (int c_ = 0; c_ < 4; c_++) {                                \
                const int u_ = 4 * g_ + c_;                                 \
                float e_ = si + dd_[c_];                                    \
                e_ = e_ > 0.f ? e_ : 0.2f * e_;                             \
                float p_ = ((aw_ >> u_) & 1u) ? __expf(e_) : 0.f;           \
                p_ = tf32r(p_);                                             \
                lsum += p_;                                                 \
                pv_[u_] = p_;                                               \
            }                                                               \
        }                                                                   \
        if constexpr (PG == 4) {                                            \
            float2* pb_ = (float2*)((pbuf_) + prow * PST + kbase);          \
            _Pragma("unroll")                                               \
            for (int c_ = 0; c_ < 4; c_++)                                  \
                pb_[c_] = make_float2(pv_[c_], pv_[c_ + 4]);                \
        } else {                                                            \
            float* pb_ = (pbuf_) + prow * PST + kbase;                      \
            _Pragma("unroll")                                               \
            for (int g_ = 0; g_ < KPT / 4; g_++)                            \
                *(float4*)(pb_ + 4 * g_) = make_float4(                     \
                    pv_[4*g_], pv_[4*g_+1], pv_[4*g_+2], pv_[4*g_+3]);      \
        }                                                                   \
    }

#define ISSUE_WH(kt_, buf_)                                                 \
    {                                                                       \
        const float* wp_ = wsrc0 + (size_t)(kt_) * 32 * FH;                 \
        const uint32_t wd_ = wdst0 + (uint32_t)(buf_) * 16u * WR2P * 4u;    \
        _Pragma("unroll")                                                   \
        for (int q_ = 0; q_ < 4; q_++)                                      \
            cp16(wd_ + q_ * 128u * 4u, wp_ + q_ * 128);                     \
    }

#define PREP_STEP(kt_)                                                      \
    {                                                                       \
        if ((kt_) + 2 < NKT) { ISSUE_WH((kt_) + 2, ((kt_) + 2) % 3); }      \
        cp_commit();                                                        \
        if ((kt_) + 1 < NKT) {                                              \
            COMPUTE_P((kt_) + 1, Ps + (((kt_) + 1) & 1) * ROWS * PST);      \
        }                                                                   \
    }

#define MMA_STEP(kt_)                                                       \
    {                                                                       \
        const float* pB = Ps + ((kt_) & 1) * ROWS * PST;                    \
        const float* wB = Whs + ((kt_) % 3) * 16 * WR2P;                    \
        _Pragma("unroll")                                                   \
        for (int kk = 0; kk < 4; kk++) {                                    \
            uint32_t a[MT][4];                                              \
            _Pragma("unroll")                                               \
            for (int mt = 0; mt < MT; mt++) {                               \
                const int row_ = wr * 16 * MT + mt * 16 + ar;               \
                if constexpr (PG == 4) {                                    \
                    const float* pr = pB + row_ * PST + kk * 8 + 2 * ak;    \
                    float2 q0 = *(const float2*)pr;                         \
                    float2 q1 = *(const float2*)(pr + 8 * PST);             \
                    a[mt][0] = __float_as_uint(q0.x);                       \
                    a[mt][1] = __float_as_uint(q1.x);                       \
                    a[mt][2] = __float_as_uint(q0.y);                       \
                    a[mt][3] = __float_as_uint(q1.y);                       \
                } else {                                                    \
                    const float* pr = pB + row_ * PST + kk * 8 + ak;        \
                    a[mt][0] = __float_as_uint(pr[0]);                      \
                    a[mt][1] = __float_as_uint(pr[8 * PST]);                \
                    a[mt][2] = __float_as_uint(pr[4]);                      \
                    a[mt][3] = __float_as_uint(pr[8 * PST + 4]);            \
                }                                                           \
            }                                                               \
            _Pragma("unroll")                                               \
            for (int nt = 0; nt < 8; nt++) {                                \
                const int n = wc * 64 + nt * 8 + ar;                        \
                float2 bb_ = *(const float2*)(wB + (kk * 4 + ak) * WR2P     \
                                              + 2 * n);                     \
                uint32_t b0 = __float_as_uint(bb_.x);                       \
                uint32_t b1 = __float_as_uint(bb_.y);                       \
                _Pragma("unroll")                                           \
                for (int mt = 0; mt < MT; mt++)                             \
                    mma_tf32(d[mt][nt], a[mt], b0, b1);                     \
            }                                                               \
        }                                                                   \
    }

    // ---- prologue ----
    ISSUE_WH(0, 0); cp_commit();
    if (1 < NKT) { ISSUE_WH(1, 1); }
    cp_commit();
    COMPUTE_P(0, Ps);

    for (int kt = 0; kt < NKT; kt++) {
        cp_wait1();          // Wh(kt) complete (per-thread)
        __syncthreads();     // visibility; prev MMA reads done
        if (mmaFirst) {
            MMA_STEP(kt);
            PREP_STEP(kt);
        } else {
            PREP_STEP(kt);
            MMA_STEP(kt);
        }
    }
    __syncthreads();
    lpart[tid] = lsum;       // lpart[prow*PG + sub]
    __syncthreads();

    if (PARTIAL) {
        float* np = g_np + (size_t)blockIdx.y * NV * FO;
#pragma unroll
        for (int mt = 0; mt < MT; mt++) {
            const int r0 = wr * 16 * MT + mt * 16 + ar;
            const int r1 = r0 + 8;
#pragma unroll
            for (int nt = 0; nt < 8; nt++) {
                const int c = wc * 64 + nt * 8 + 2 * ak;
                *(float2*)(np + (size_t)(i0 + r0) * FO + c) = make_float2(d[mt][nt][0], d[mt][nt][1]);
                *(float2*)(np + (size_t)(i0 + r1) * FO + c) = make_float2(d[mt][nt][2], d[mt][nt][3]);
            }
        }
        if (tid < ROWS) {
            float l = 0.f;
#pragma unroll
            for (int g = 0; g < PG; g++) l += lpart[tid * PG + g];
            g_lp[blockIdx.y * NV + i0 + tid] = l;
        }
    } else {
        float* out = g_h1;
        const int coloff = blockIdx.z * FH;
#pragma unroll
        for (int mt = 0; mt < MT; mt++) {
            const int r0 = wr * 16 * MT + mt * 16 + ar;
            const int r1 = r0 + 8;
            float l0 = 0.f, l1 = 0.f;
#pragma unroll
            for (int g = 0; g < PG; g++) {
                l0 += lpart[r0 * PG + g];
                l1 += lpart[r1 * PG + g];
            }
            const float rl0 = 1.0f / l0, rl1 = 1.0f / l1;
#pragma unroll
            for (int nt = 0; nt < 8; nt++) {
                const int c = coloff + wc * 64 + nt * 8 + 2 * ak;
                float o0 = d[mt][nt][0] * rl0, o1 = d[mt][nt][1] * rl0;
                float o2 = d[mt][nt][2] * rl1, o3 = d[mt][nt][3] * rl1;
                o0 = o0 > 0.f ? o0 : (__expf(o0) - 1.0f);
                o1 = o1 > 0.f ? o1 : (__expf(o1) - 1.0f);
                o2 = o2 > 0.f ? o2 : (__expf(o2) - 1.0f);
                o3 = o3 > 0.f ? o3 : (__expf(o3) - 1.0f);
                *(float2*)(out + (size_t)(i0 + r0) * F2 + c) = make_float2(o0, o1);
                *(float2*)(out + (size_t)(i0 + r1) * F2 + c) = make_float2(o2, o3);
            }
        }
    }
#undef COMPUTE_P
#undef ISSUE_WH
#undef PREP_STEP
#undef MMA_STEP
}

// ---------------- K4: combine split partials (layer 1 epilogue) --------------
__global__ void combine_kernel(float* __restrict__ out) {
    const int i = blockIdx.x;
    const int c = threadIdx.x;
    const float l = g_lp[i] + g_lp[NV + i];
    const float n = g_np[(size_t)i * FO + c] +
                    g_np[(size_t)NV * FO + (size_t)i * FO + c];
    out[(size_t)i * FO + c] = n / l;
}

// ---------------- launch -----------------------------------------------------
extern "C" void kernel_launch(void* const* d_in, const int* in_sizes, int n_in,
                              void* d_out, int out_size) {
    (void)in_sizes; (void)n_in; (void)out_size;
    const float* x   = (const float*)d_in[0];
    const int*   adj = (const int*)d_in[1];
    const float* W1  = (const float*)d_in[2];
    const float* a1  = (const float*)d_in[3];
    const float* W2  = (const float*)d_in[4];
    const float* a2  = (const float*)d_in[5];
    float* out = (float*)d_out;

    static int inited = 0;
    if (!inited) {
        cudaFuncSetAttribute(gemm_tf32_kernel<128>,
            cudaFuncAttributeMaxDynamicSharedMemorySize, GEMM_SMEM(128));
        cudaFuncSetAttribute(gemm_tf32_kernel<64>,
            cudaFuncAttributeMaxDynamicSharedMemorySize, GEMM_SMEM(64));
        cudaFuncSetAttribute(attn_kernel<128, 0>,
            cudaFuncAttributeMaxDynamicSharedMemorySize, ATTN_SMEM(128));
        cudaFuncSetAttribute(attn_kernel<64, 1>,
            cudaFuncAttributeMaxDynamicSharedMemorySize, ATTN_SMEM(64));
        inited = 1;
    }

    float* Wh1p;  cudaGetSymbolAddress((void**)&Wh1p,  g_Wh1);
    float* Wh1pp; cudaGetSymbolAddress((void**)&Wh1pp, g_Wh1P);
    float* h1p;   cudaGetSymbolAddress((void**)&h1p,   g_h1);
    float* Wh2p;  cudaGetSymbolAddress((void**)&Wh2p,  g_Wh2);
    float* Wh2pp; cudaGetSymbolAddress((void**)&Wh2pp, g_Wh2P);

    adjbits_kernel<<<(NV * NV) / 256, 256>>>(adj);
    gemm_tf32_kernel<128><<<dim3(NV / 128, NHEADS), 512, GEMM_SMEM(128)>>>(
        x, W1, Wh1p, Wh1pp, F1, (long)F1 * FH, (long)NV * FH);
    srcdst_kernel<<<dim3(NV / 8, NHEADS), 256>>>(a1, 0);
    attn_kernel<128, 0><<<dim3(NV / 128, 1, NHEADS), 512, ATTN_SMEM(128)>>>();
    gemm_tf32_kernel<64><<<dim3(NV / 64, 1), 512, GEMM_SMEM(64)>>>(
        h1p, W2, Wh2p, Wh2pp, F2, 0L, 0L);
    srcdst_kernel<<<dim3(NV / 8, 1), 256>>>(a2, 1);
    attn_kernel<64, 1><<<dim3(NV / 64, 2), 512, ATTN_SMEM(64)>>>();
    combine_kernel<<<NV, 256>>>(out);
}

// round 10
// speedup vs baseline: 2.4875x; 1.3361x over previous
#include <cuda_runtime.h>
#include <cuda_fp16.h>
#include <cstdint>

#define NV 4096
#define F1 512
#define FH 256
#define NHEADS 4
#define F2 1024   // nhid * nheads
#define FO 256
#define NW (NV/32) // 128 bitmask words per row

#define PSROW 36   // gemm A tile row stride (words)
#define WROW  264  // gemm B tile row stride (words)
#define PSTW  40   // attn P tile row stride (words), XOR-swizzled groups
#define WBW   520  // attn Wh buf row stride (words): 520%32==8 -> uint2 conflict-free

// ---------------- scratch (static device memory; no allocations) ------------
__device__ __align__(16) float  g_Wh1[NHEADS * NV * FH];   // row-major fp32 (srcdst)
__device__ __align__(16) __half g_Wh1P[NHEADS * NV * FH];  // packed fp16 B-frag layout
__device__ __align__(16) float  g_h1[NV * F2];
__device__ __align__(16) float  g_Wh2[NV * FO];
__device__ __align__(16) __half g_Wh2P[NV * FO];
__device__ __align__(16) float  g_src1[NHEADS * NV];
__device__ __align__(16) float  g_dst1[NHEADS * NV];
__device__ __align__(16) float  g_src2[NV];
__device__ __align__(16) float  g_dst2[NV];
__device__ __align__(16) float  g_np[2 * NV * FO];       // L1 split numerators
__device__ __align__(16) float  g_lp[2 * NV];            // L1 split denominators
__device__ __align__(16) unsigned g_adjbits[NV * NW];    // 2 MB

// ---------------- helpers -----------------------------------------------------
__device__ __forceinline__ float tf32r(float x) {
    uint32_t u;
    asm("cvt.rna.tf32.f32 %0, %1;" : "=r"(u) : "f"(x));
    return __uint_as_float(u);
}
__device__ __forceinline__ uint32_t f2h2(float a, float b) {
    __half2 h = __floats2half2_rn(a, b);
    return *reinterpret_cast<uint32_t*>(&h);
}
__device__ __forceinline__ void mma_tf32(float* d, const uint32_t* a,
                                         uint32_t b0, uint32_t b1) {
    asm volatile(
        "mma.sync.aligned.m16n8k8.row.col.f32.tf32.tf32.f32 "
        "{%0,%1,%2,%3}, {%4,%5,%6,%7}, {%8,%9}, {%0,%1,%2,%3};"
        : "+f"(d[0]), "+f"(d[1]), "+f"(d[2]), "+f"(d[3])
        : "r"(a[0]), "r"(a[1]), "r"(a[2]), "r"(a[3]), "r"(b0), "r"(b1));
}
__device__ __forceinline__ void mma_f16(float* d, const uint32_t* a,
                                        uint32_t b0, uint32_t b1) {
    asm volatile(
        "mma.sync.aligned.m16n8k16.row.col.f32.f16.f16.f32 "
        "{%0,%1,%2,%3}, {%4,%5,%6,%7}, {%8,%9}, {%0,%1,%2,%3};"
        : "+f"(d[0]), "+f"(d[1]), "+f"(d[2]), "+f"(d[3])
        : "r"(a[0]), "r"(a[1]), "r"(a[2]), "r"(a[3]), "r"(b0), "r"(b1));
}
__device__ __forceinline__ void cp16(uint32_t saddr, const void* gptr) {
    asm volatile("cp.async.cg.shared.global [%0], [%1], 16;"
                 :: "r"(saddr), "l"(gptr));
}
__device__ __forceinline__ void cp_commit() {
    asm volatile("cp.async.commit_group;");
}
__device__ __forceinline__ void cp_wait1() {
    asm volatile("cp.async.wait_group 1;");
}
// packed fp16 layout: per 32-node block, 8 group-rows of 256*(4 halves);
// node jl -> group g = (jl>>4)*4 + ((jl&7)>>1), slot = (jl&1) + ((jl>>3)&1)*2
__device__ __forceinline__ size_t packed_base(int R) {
    int blk = R >> 5, jl = R & 31;
    int g = (jl >> 4) * 4 + ((jl & 7) >> 1);
    int slot = (jl & 1) + ((jl >> 3) & 1) * 2;
    return (size_t)blk * 8192 + (size_t)g * 1024 + slot;
}

// ---------------- K0: adjacency -> bitmask ----------------------------------
__global__ void adjbits_kernel(const int* __restrict__ adj) {
    int idx = blockIdx.x * blockDim.x + threadIdx.x;   // over NV*NV
    unsigned bit = (adj[idx] != 0) ? 1u : 0u;
    unsigned w = __ballot_sync(0xffffffffu, bit);
    if ((threadIdx.x & 31) == 0) g_adjbits[idx >> 5] = w;
}

// ---------------- K1: tf32 mma GEMM  C[*,256] = A[*,K] @ B[K,256] ------------
// Writes C row-major fp32 AND packed fp16 Cp for the attn B feed.
template <int ROWS>
__global__ void __launch_bounds__(512, 1)
gemm_tf32_kernel(const float* __restrict__ A, const float* __restrict__ B,
                 float* __restrict__ C, __half* __restrict__ Cp,
                 int K, long bStride, long cStride) {
    constexpr int MT = ROWS / 64;
    constexpr int TPR = 512 / ROWS;     // threads per A-row
    constexpr int AK  = 32 / TPR;       // A cols per thread
    extern __shared__ char smem[];
    float* As = (float*)smem;                            // [2][ROWS*PSROW]
    float* Bs = (float*)(smem + 2 * ROWS * PSROW * 4);   // [2][32*WROW]

    const int tid = threadIdx.x;
    const int wid = tid >> 5, lane = tid & 31;
    const int wr = wid >> 2, wc = wid & 3;
    const float* Bb = B + (size_t)blockIdx.y * bStride;
    float* Cb   = C  + (size_t)blockIdx.y * cStride;
    __half* Cpb = Cp + (size_t)blockIdx.y * cStride;
    const int i0 = blockIdx.x * ROWS;

    const int arow = tid / TPR, ak0 = (tid % TPR) * AK;
    const int jrow = tid >> 4, fbase = (tid & 15) * 4;
    const int ar = lane >> 2, ak = lane & 3;

    float d[MT][8][4];
#pragma unroll
    for (int mt = 0; mt < MT; mt++)
#pragma unroll
        for (int nt = 0; nt < 8; nt++)
#pragma unroll
            for (int v = 0; v < 4; v++) d[mt][nt][v] = 0.f;

    const int NKT = K / 32;
    for (int kt = 0; kt < NKT; kt++) {
        const int bb = kt & 1;
        const int k0g = kt * 32;
        {
            const float* wp = Bb + (size_t)(k0g + jrow) * FH + fbase;
            float* bs = Bs + bb * 32 * WROW + jrow * WROW + fbase;
#pragma unroll
            for (int q = 0; q < 4; q++) {
                float4 v = *(const float4*)(wp + 64 * q);
                *(float4*)(bs + 64 * q) =
                    make_float4(tf32r(v.x), tf32r(v.y), tf32r(v.z), tf32r(v.w));
            }
            const float* ap = A + (size_t)(i0 + arow) * K + k0g + ak0;
            float* as = As + bb * ROWS * PSROW + arow * PSROW + ak0;
#pragma unroll
            for (int q = 0; q < AK / 4; q++) {
                float4 v = *(const float4*)(ap + 4 * q);
                *(float4*)(as + 4 * q) =
                    make_float4(tf32r(v.x), tf32r(v.y), tf32r(v.z), tf32r(v.w));
            }
        }
        __syncthreads();
        const float* pB = As + bb * ROWS * PSROW;
        const float* wB = Bs + bb * 32 * WROW;
#pragma unroll
        for (int kk = 0; kk < 4; kk++) {
            const int k0 = kk * 8;
            uint32_t a[MT][4];
#pragma unroll
            for (int mt = 0; mt < MT; mt++) {
                const float* pr = pB + (wr * 16 * MT + mt * 16 + ar) * PSROW + k0 + ak;
                a[mt][0] = __float_as_uint(pr[0]);
                a[mt][1] = __float_as_uint(pr[8 * PSROW]);
                a[mt][2] = __float_as_uint(pr[4]);
                a[mt][3] = __float_as_uint(pr[8 * PSROW + 4]);
            }
#pragma unroll
            for (int nt = 0; nt < 8; nt++) {
                const int n = wc * 64 + nt * 8 + ar;
                uint32_t b0 = __float_as_uint(wB[(k0 + ak) * WROW + n]);
                uint32_t b1 = __float_as_uint(wB[(k0 + ak + 4) * WROW + n]);
#pragma unroll
                for (int mt = 0; mt < MT; mt++)
                    mma_tf32(d[mt][nt], a[mt], b0, b1);
            }
        }
        __syncthreads();
    }
#pragma unroll
    for (int mt = 0; mt < MT; mt++) {
        const int r0 = wr * 16 * MT + mt * 16 + ar;
        const int r1 = r0 + 8;
        const int R0 = i0 + r0, R1 = i0 + r1;
        const size_t pb0 = packed_base(R0), pb1 = packed_base(R1);
#pragma unroll
        for (int nt = 0; nt < 8; nt++) {
            const int c = wc * 64 + nt * 8 + 2 * ak;
            float t0 = d[mt][nt][0], t1 = d[mt][nt][1];
            float t2 = d[mt][nt][2], t3 = d[mt][nt][3];
            *(float2*)(Cb + (size_t)R0 * FH + c) = make_float2(t0, t1);
            *(float2*)(Cb + (size_t)R1 * FH + c) = make_float2(t2, t3);
            Cpb[pb0 + (size_t)c * 4]       = __float2half_rn(t0);
            Cpb[pb0 + (size_t)(c + 1) * 4] = __float2half_rn(t1);
            Cpb[pb1 + (size_t)c * 4]       = __float2half_rn(t2);
            Cpb[pb1 + (size_t)(c + 1) * 4] = __float2half_rn(t3);
        }
    }
}

#define GEMM_SMEM(R) (2 * (R) * PSROW * 4 + 2 * 32 * WROW * 4)

// ---------------- K2: src/dst projections (exact fp32) -----------------------
__global__ void srcdst_kernel(const float* __restrict__ avec, int layer) {
    __shared__ float sa[2 * FH];
    const int b = blockIdx.y;
    const float* Wh = layer ? g_Wh2 : g_Wh1 + (size_t)b * NV * FH;
    const float* a  = avec + b * 2 * FH;
    float* src = layer ? g_src2 : g_src1 + b * NV;
    float* dst = layer ? g_dst2 : g_dst1 + b * NV;

    const int tid = threadIdx.x;
    for (int i = tid; i < 2 * FH; i += blockDim.x) sa[i] = a[i];
    __syncthreads();

    const int warp = tid >> 5, lane = tid & 31;
    const int row = blockIdx.x * 8 + warp;
    const float* wr = Wh + (size_t)row * FH;
    float s1 = 0.f, s2 = 0.f;
#pragma unroll
    for (int v = lane; v < FH; v += 32) {
        float w = wr[v];
        s1 += w * sa[v];
        s2 += w * sa[FH + v];
    }
#pragma unroll
    for (int o = 16; o; o >>= 1) {
        s1 += __shfl_xor_sync(0xffffffffu, s1, o);
        s2 += __shfl_xor_sync(0xffffffffu, s2, o);
    }
    if (lane == 0) { src[row] = s1; dst[row] = s2; }
}

// ---------------- K3: fp16 mma fused attention -------------------------------
// cp.async packed-fp16 Wh feed (3 bufs, depth 2), per-SMSP phase stagger,
// m16n8k16 f16 MMA with fp32 accumulate. P tile fp16 groups, XOR swizzle.
#define ATTN_SMEM(R) (2 * (R) * PSTW * 4 + 3 * 8 * WBW * 4 + 512 * 4)

template <int ROWS, int PARTIAL>
__global__ void __launch_bounds__(512, 1)
attn_kernel() {
    constexpr int MT = ROWS / 64;
    constexpr int PG = 512 / ROWS;      // threads per P-row (4 or 8)
    extern __shared__ char smem[];
    float* Ps    = (float*)smem;                          // [2][ROWS*PSTW]
    float* Whs   = (float*)(smem + 2 * ROWS * PSTW * 4);  // [3][8*WBW]
    float* lpart = (float*)(smem + 2 * ROWS * PSTW * 4 + 3 * 8 * WBW * 4);
    const uint32_t whs_s = (uint32_t)__cvta_generic_to_shared(Whs);

    const int tid = threadIdx.x;
    const int wid = tid >> 5, lane = tid & 31;
    const int wr = wid >> 2, wc = wid & 3;
    const int i0 = blockIdx.x * ROWS;
    const bool mmaFirst = ((wid >> 2) & 1) != 0;   // per-SMSP 2/2 split

    const __half* WhP; const float* srcT; const float* dR;
    int jbase, NKT;
    if (PARTIAL) {
        WhP = g_Wh2P; srcT = g_src2; dR = g_dst2;
        jbase = blockIdx.y * (NV / 2); NKT = (NV / 2) / 32;
    } else {
        const int b = blockIdx.z;
        WhP = g_Wh1P + (size_t)b * NV * FH;
        srcT = g_src1 + b * NV; dR = g_dst1 + b * NV;
        jbase = 0; NKT = NV / 32;
    }

    const int prow = tid / PG;
    const int q_   = tid % PG;
    const float si = srcT[i0 + prow];
    const unsigned* adjrow = g_adjbits + (size_t)(i0 + prow) * NW + (jbase >> 5);
    const int ar = lane >> 2, ak = lane & 3;

    // cp.async mapping: thread -> (group row g = tid>>6, 16B chunk = tid&63)
    const __half* wsrc0 = WhP + (size_t)(jbase >> 5) * 8192 +
                          (size_t)(tid >> 6) * 1024 + (size_t)(tid & 63) * 8;
    const uint32_t wdst0 = whs_s +
                           (uint32_t)((tid >> 6) * WBW + (tid & 63) * 4) * 4u;

    float d[MT][8][4];
#pragma unroll
    for (int mt = 0; mt < MT; mt++)
#pragma unroll
        for (int nt = 0; nt < 8; nt++)
#pragma unroll
            for (int v = 0; v < 4; v++) d[mt][nt][v] = 0.f;
    float lsum = 0.f;

#define COMPUTE_P(kt_, pbuf_)                                                 \
    {                                                                         \
        const int j0_ = jbase + (kt_) * 32;                                   \
        const unsigned aw_ = adjrow[kt_];                                     \
        uint2* pr_ = (uint2*)((pbuf_) + prow * PSTW);                         \
        const int s_ = prow & 7;                                              \
        if constexpr (PG == 4) {                                              \
            const int kb_ = (q_ < 2) ? 4 * q_ : 4 * q_ + 8;                   \
            float4 dv1 = *(const float4*)(dR + j0_ + kb_);                    \
            float4 dv2 = *(const float4*)(dR + j0_ + kb_ + 8);                \
            float dd_[8] = {dv1.x, dv1.y, dv1.z, dv1.w,                       \
                            dv2.x, dv2.y, dv2.z, dv2.w};                      \
            float p_[8];                                                      \
            _Pragma("unroll")                                                 \
            for (int u_ = 0; u_ < 8; u_++) {                                  \
                float e_ = si + dd_[u_];                                      \
                e_ = fmaxf(e_, 0.2f * e_);                                    \
                float pp_ = __expf(e_);                                       \
                pp_ = fminf(pp_, 65000.f);                                    \
                const int bit_ = kb_ + ((u_ < 4) ? u_ : u_ + 4);              \
                pp_ = ((aw_ >> bit_) & 1u) ? pp_ : 0.f;                       \
                lsum += pp_;                                                  \
                p_[u_] = pp_;                                                 \
            }                                                                 \
            const int g0_ = 2 * q_;                                           \
            pr_[g0_ ^ s_]       = make_uint2(f2h2(p_[0], p_[1]),              \
                                             f2h2(p_[4], p_[5]));             \
            pr_[(g0_ + 1) ^ s_] = make_uint2(f2h2(p_[2], p_[3]),              \
                                             f2h2(p_[6], p_[7]));             \
        } else {                                                              \
            const int kb_ = 16 * (q_ >> 2) + 2 * (q_ & 3);                    \
            float2 dv1 = *(const float2*)(dR + j0_ + kb_);                    \
            float2 dv2 = *(const float2*)(dR + j0_ + kb_ + 8);                \
            float dd_[4] = {dv1.x, dv1.y, dv2.x, dv2.y};                      \
            float p_[4];                                                      \
            _Pragma("unroll")                                                 \
            for (int u_ = 0; u_ < 4; u_++) {                                  \
                float e_ = si + dd_[u_];                                      \
                e_ = fmaxf(e_, 0.2f * e_);                                    \
                float pp_ = __expf(e_);                                       \
                pp_ = fminf(pp_, 65000.f);                                    \
                const int bit_ = kb_ + ((u_ < 2) ? u_ : u_ + 6);              \
                pp_ = ((aw_ >> bit_) & 1u) ? pp_ : 0.f;                       \
                lsum += pp_;                                                  \
                p_[u_] = pp_;                                                 \
            }                                                                 \
            pr_[q_ ^ s_] = make_uint2(f2h2(p_[0], p_[1]),                     \
                                      f2h2(p_[2], p_[3]));                    \
        }                                                                     \
    }

#define ISSUE_WH(kt_, buf_)                                                   \
    {                                                                         \
        const __half* wp_ = wsrc0 + (size_t)(kt_) * 8192;                     \
        const uint32_t wd_ = wdst0 + (uint32_t)(buf_) * (8u * WBW * 4u);      \
        cp16(wd_, wp_);                                                       \
        cp16(wd_ + 1024u, wp_ + 512);                                         \
    }

#define PREP_STEP(kt_)                                                        \
    {                                                                         \
        if ((kt_) + 2 < NKT) { ISSUE_WH((kt_) + 2, ((kt_) + 2) % 3); }        \
        cp_commit();                                                          \
        if ((kt_) + 1 < NKT) {                                                \
            COMPUTE_P((kt_) + 1, Ps + (((kt_) + 1) & 1) * ROWS * PSTW);       \
        }                                                                     \
    }

#define MMA_STEP(kt_)                                                         \
    {                                                                         \
        const float* pB = Ps + ((kt_) & 1) * ROWS * PSTW;                     \
        const float* wB = Whs + ((kt_) % 3) * 8 * WBW;                        \
        _Pragma("unroll")                                                     \
        for (int kk = 0; kk < 2; kk++) {                                      \
            uint32_t a[MT][4];                                                \
            _Pragma("unroll")                                                 \
            for (int mt = 0; mt < MT; mt++) {                                 \
                const int row_ = wr * 16 * MT + mt * 16 + ar;                 \
                const int gi_ = (kk * 4 + ak) ^ ar;                           \
                uint2 u_ = ((const uint2*)(pB + row_ * PSTW))[gi_];           \
                uint2 v_ = ((const uint2*)(pB + (row_ + 8) * PSTW))[gi_];     \
                a[mt][0] = u_.x; a[mt][1] = v_.x;                             \
                a[mt][2] = u_.y; a[mt][3] = v_.y;                             \
            }                                                                 \
            _Pragma("unroll")                                                 \
            for (int nt = 0; nt < 8; nt++) {                                  \
                const int n = wc * 64 + nt * 8 + ar;                          \
                uint2 b_ = ((const uint2*)(wB + (kk * 4 + ak) * WBW))[n];     \
                _Pragma("unroll")                                             \
                for (int mt = 0; mt < MT; mt++)                               \
                    mma_f16(d[mt][nt], a[mt], b_.x, b_.y);                    \
            }                                                                 \
        }                                                                     \
    }

    // ---- prologue ----
    ISSUE_WH(0, 0); cp_commit();
    if (1 < NKT) { ISSUE_WH(1, 1); }
    cp_commit();
    COMPUTE_P(0, Ps);

    for (int kt = 0; kt < NKT; kt++) {
        cp_wait1();          // Wh(kt) complete (per-thread)
        __syncthreads();     // visibility; prev MMA reads done
        if (mmaFirst) {
            MMA_STEP(kt);
            PREP_STEP(kt);
        } else {
            PREP_STEP(kt);
            MMA_STEP(kt);
        }
    }
    __syncthreads();
    lpart[tid] = lsum;       // lpart[prow*PG + q]
    __syncthreads();

    if (PARTIAL) {
        float* np = g_np + (size_t)blockIdx.y * NV * FO;
#pragma unroll
        for (int mt = 0; mt < MT; mt++) {
            const int r0 = wr * 16 * MT + mt * 16 + ar;
            const int r1 = r0 + 8;
#pragma unroll
            for (int nt = 0; nt < 8; nt++) {
                const int c = wc * 64 + nt * 8 + 2 * ak;
                *(float2*)(np + (size_t)(i0 + r0) * FO + c) = make_float2(d[mt][nt][0], d[mt][nt][1]);
                *(float2*)(np + (size_t)(i0 + r1) * FO + c) = make_float2(d[mt][nt][2], d[mt][nt][3]);
            }
        }
        if (tid < ROWS) {
            float l = 0.f;
#pragma unroll
            for (int g = 0; g < PG; g++) l += lpart[tid * PG + g];
            g_lp[blockIdx.y * NV + i0 + tid] = l;
        }
    } else {
        float* out = g_h1;
        const int coloff = blockIdx.z * FH;
#pragma unroll
        for (int mt = 0; mt < MT; mt++) {
            const int r0 = wr * 16 * MT + mt * 16 + ar;
            const int r1 = r0 + 8;
            float l0 = 0.f, l1 = 0.f;
#pragma unroll
            for (int g = 0; g < PG; g++) {
                l0 += lpart[r0 * PG + g];
                l1 += lpart[r1 * PG + g];
            }
            const float rl0 = 1.0f / l0, rl1 = 1.0f / l1;
#pragma unroll
            for (int nt = 0; nt < 8; nt++) {
                const int c = coloff + wc * 64 + nt * 8 + 2 * ak;
                float o0 = d[mt][nt][0] * rl0, o1 = d[mt][nt][1] * rl0;
                float o2 = d[mt][nt][2] * rl1, o3 = d[mt][nt][3] * rl1;
                o0 = o0 > 0.f ? o0 : (__expf(o0) - 1.0f);
                o1 = o1 > 0.f ? o1 : (__expf(o1) - 1.0f);
                o2 = o2 > 0.f ? o2 : (__expf(o2) - 1.0f);
                o3 = o3 > 0.f ? o3 : (__expf(o3) - 1.0f);
                *(float2*)(out + (size_t)(i0 + r0) * F2 + c) = make_float2(o0, o1);
                *(float2*)(out + (size_t)(i0 + r1) * F2 + c) = make_float2(o2, o3);
            }
        }
    }
#undef COMPUTE_P
#undef ISSUE_WH
#undef PREP_STEP
#undef MMA_STEP
}

// ---------------- K4: combine split partials (layer 1 epilogue) --------------
__global__ void combine_kernel(float* __restrict__ out) {
    const int i = blockIdx.x;
    const int c = threadIdx.x;
    const float l = g_lp[i] + g_lp[NV + i];
    const float n = g_np[(size_t)i * FO + c] +
                    g_np[(size_t)NV * FO + (size_t)i * FO + c];
    out[(size_t)i * FO + c] = n / l;
}

// ---------------- launch -----------------------------------------------------
extern "C" void kernel_launch(void* const* d_in, const int* in_sizes, int n_in,
                              void* d_out, int out_size) {
    (void)in_sizes; (void)n_in; (void)out_size;
    const float* x   = (const float*)d_in[0];
    const int*   adj = (const int*)d_in[1];
    const float* W1  = (const float*)d_in[2];
    const float* a1  = (const float*)d_in[3];
    const float* W2  = (const float*)d_in[4];
    const float* a2  = (const float*)d_in[5];
    float* out = (float*)d_out;

    static int inited = 0;
    if (!inited) {
        cudaFuncSetAttribute(gemm_tf32_kernel<128>,
            cudaFuncAttributeMaxDynamicSharedMemorySize, GEMM_SMEM(128));
        cudaFuncSetAttribute(gemm_tf32_kernel<64>,
            cudaFuncAttributeMaxDynamicSharedMemorySize, GEMM_SMEM(64));
        cudaFuncSetAttribute(attn_kernel<128, 0>,
            cudaFuncAttributeMaxDynamicSharedMemorySize, ATTN_SMEM(128));
        cudaFuncSetAttribute(attn_kernel<64, 1>,
            cudaFuncAttributeMaxDynamicSharedMemorySize, ATTN_SMEM(64));
        inited = 1;
    }

    float*  Wh1p;  cudaGetSymbolAddress((void**)&Wh1p,  g_Wh1);
    __half* Wh1pp; cudaGetSymbolAddress((void**)&Wh1pp, g_Wh1P);
    float*  h1p;   cudaGetSymbolAddress((void**)&h1p,   g_h1);
    float*  Wh2p;  cudaGetSymbolAddress((void**)&Wh2p,  g_Wh2);
    __half* Wh2pp; cudaGetSymbolAddress((void**)&Wh2pp, g_Wh2P);

    adjbits_kernel<<<(NV * NV) / 256, 256>>>(adj);
    gemm_tf32_kernel<128><<<dim3(NV / 128, NHEADS), 512, GEMM_SMEM(128)>>>(
        x, W1, Wh1p, Wh1pp, F1, (long)F1 * FH, (long)NV * FH);
    srcdst_kernel<<<dim3(NV / 8, NHEADS), 256>>>(a1, 0);
    attn_kernel<128, 0><<<dim3(NV / 128, 1, NHEADS), 512, ATTN_SMEM(128)>>>();
    gemm_tf32_kernel<64><<<dim3(NV / 64, 1), 512, GEMM_SMEM(64)>>>(
        h1p, W2, Wh2p, Wh2pp, F2, 0L, 0L);
    srcdst_kernel<<<dim3(NV / 8, 1), 256>>>(a2, 1);
    attn_kernel<64, 1><<<dim3(NV / 64, 2), 512, ATTN_SMEM(64)>>>();
    combine_kernel<<<NV, 256>>>(out);
}

// round 11
// speedup vs baseline: 2.7069x; 1.0882x over previous
#include <cuda_runtime.h>
#include <cuda_fp16.h>
#include <cstdint>

#define NV 4096
#define F1 512
#define FH 256
#define NHEADS 4
#define F2 1024   // nhid * nheads
#define FO 256
#define NW (NV/32) // 128 bitmask words per row

#define PSROW 36   // gemm A tile row stride (words)
#define WROW  264  // gemm B tile row stride (words)
#define PSTW  40   // attn P tile row stride (words; 32 used), swizzled groups
#define WBW   520  // attn Wh buf row stride (words; 512 used): 520%32==8

// ---------------- scratch (static device memory; no allocations) ------------
__device__ __align__(16) float  g_Wh1[NHEADS * NV * FH];   // row-major fp32 (srcdst)
__device__ __align__(16) __half g_Wh1P[NHEADS * NV * FH];  // packed fp16 B-frag layout
__device__ __align__(16) float  g_h1[NV * F2];
__device__ __align__(16) float  g_Wh2[NV * FO];
__device__ __align__(16) __half g_Wh2P[NV * FO];
__device__ __align__(16) float  g_src1[NHEADS * NV];
__device__ __align__(16) float  g_dst1[NHEADS * NV];
__device__ __align__(16) float  g_src2[NV];
__device__ __align__(16) float  g_dst2[NV];
__device__ __align__(16) float  g_np[4 * NV * FO];       // L1 split numerators
__device__ __align__(16) float  g_lp[4 * NV];            // L1 split denominators
__device__ __align__(16) unsigned g_adjbits[NV * NW];    // 2 MB

// ---------------- helpers -----------------------------------------------------
__device__ __forceinline__ float tf32r(float x) {
    uint32_t u;
    asm("cvt.rna.tf32.f32 %0, %1;" : "=r"(u) : "f"(x));
    return __uint_as_float(u);
}
__device__ __forceinline__ uint32_t f2h2(float a, float b) {
    __half2 h = __floats2half2_rn(a, b);
    return *reinterpret_cast<uint32_t*>(&h);
}
__device__ __forceinline__ void mma_tf32(float* d, const uint32_t* a,
                                         uint32_t b0, uint32_t b1) {
    asm volatile(
        "mma.sync.aligned.m16n8k8.row.col.f32.tf32.tf32.f32 "
        "{%0,%1,%2,%3}, {%4,%5,%6,%7}, {%8,%9}, {%0,%1,%2,%3};"
        : "+f"(d[0]), "+f"(d[1]), "+f"(d[2]), "+f"(d[3])
        : "r"(a[0]), "r"(a[1]), "r"(a[2]), "r"(a[3]), "r"(b0), "r"(b1));
}
__device__ __forceinline__ void mma_f16(float* d, const uint32_t* a,
                                        uint32_t b0, uint32_t b1) {
    asm volatile(
        "mma.sync.aligned.m16n8k16.row.col.f32.f16.f16.f32 "
        "{%0,%1,%2,%3}, {%4,%5,%6,%7}, {%8,%9}, {%0,%1,%2,%3};"
        : "+f"(d[0]), "+f"(d[1]), "+f"(d[2]), "+f"(d[3])
        : "r"(a[0]), "r"(a[1]), "r"(a[2]), "r"(a[3]), "r"(b0), "r"(b1));
}
__device__ __forceinline__ void cp16(uint32_t saddr, const void* gptr) {
    asm volatile("cp.async.cg.shared.global [%0], [%1], 16;"
                 :: "r"(saddr), "l"(gptr));
}
__device__ __forceinline__ void cp_commit() {
    asm volatile("cp.async.commit_group;");
}
__device__ __forceinline__ void cp_wait1() {
    asm volatile("cp.async.wait_group 1;");
}
// packed fp16 layout: per 32-node block, 8 group-rows of 256*(4 halves);
// node jl -> group g = (jl>>4)*4 + ((jl&7)>>1), slot = (jl&1) + ((jl>>3)&1)*2
__device__ __forceinline__ size_t packed_base(int R) {
    int blk = R >> 5, jl = R & 31;
    int g = (jl >> 4) * 4 + ((jl & 7) >> 1);
    int slot = (jl & 1) + ((jl >> 3) & 1) * 2;
    return (size_t)blk * 8192 + (size_t)g * 1024 + slot;
}

// ---------------- K0: adjacency -> bitmask ----------------------------------
__global__ void adjbits_kernel(const int* __restrict__ adj) {
    int idx = blockIdx.x * blockDim.x + threadIdx.x;   // over NV*NV
    unsigned bit = (adj[idx] != 0) ? 1u : 0u;
    unsigned w = __ballot_sync(0xffffffffu, bit);
    if ((threadIdx.x & 31) == 0) g_adjbits[idx >> 5] = w;
}

// ---------------- K1: tf32 mma GEMM  C[*,256] = A[*,K] @ B[K,256] ------------
// Writes C row-major fp32 AND packed fp16 Cp for the attn B feed.
template <int ROWS>
__global__ void __launch_bounds__(512, 1)
gemm_tf32_kernel(const float* __restrict__ A, const float* __restrict__ B,
                 float* __restrict__ C, __half* __restrict__ Cp,
                 int K, long bStride, long cStride) {
    constexpr int MT = ROWS / 64;
    constexpr int TPR = 512 / ROWS;     // threads per A-row
    constexpr int AK  = 32 / TPR;       // A cols per thread
    extern __shared__ char smem[];
    float* As = (float*)smem;                            // [2][ROWS*PSROW]
    float* Bs = (float*)(smem + 2 * ROWS * PSROW * 4);   // [2][32*WROW]

    const int tid = threadIdx.x;
    const int wid = tid >> 5, lane = tid & 31;
    const int wr = wid >> 2, wc = wid & 3;
    const float* Bb = B + (size_t)blockIdx.y * bStride;
    float* Cb   = C  + (size_t)blockIdx.y * cStride;
    __half* Cpb = Cp + (size_t)blockIdx.y * cStride;
    const int i0 = blockIdx.x * ROWS;

    const int arow = tid / TPR, ak0 = (tid % TPR) * AK;
    const int jrow = tid >> 4, fbase = (tid & 15) * 4;
    const int ar = lane >> 2, ak = lane & 3;

    float d[MT][8][4];
#pragma unroll
    for (int mt = 0; mt < MT; mt++)
#pragma unroll
        for (int nt = 0; nt < 8; nt++)
#pragma unroll
            for (int v = 0; v < 4; v++) d[mt][nt][v] = 0.f;

    const int NKT = K / 32;
    for (int kt = 0; kt < NKT; kt++) {
        const int bb = kt & 1;
        const int k0g = kt * 32;
        {
            const float* wp = Bb + (size_t)(k0g + jrow) * FH + fbase;
            float* bs = Bs + bb * 32 * WROW + jrow * WROW + fbase;
#pragma unroll
            for (int q = 0; q < 4; q++) {
                float4 v = *(const float4*)(wp + 64 * q);
                *(float4*)(bs + 64 * q) =
                    make_float4(tf32r(v.x), tf32r(v.y), tf32r(v.z), tf32r(v.w));
            }
            const float* ap = A + (size_t)(i0 + arow) * K + k0g + ak0;
            float* as = As + bb * ROWS * PSROW + arow * PSROW + ak0;
#pragma unroll
            for (int q = 0; q < AK / 4; q++) {
                float4 v = *(const float4*)(ap + 4 * q);
                *(float4*)(as + 4 * q) =
                    make_float4(tf32r(v.x), tf32r(v.y), tf32r(v.z), tf32r(v.w));
            }
        }
        __syncthreads();
        const float* pB = As + bb * ROWS * PSROW;
        const float* wB = Bs + bb * 32 * WROW;
#pragma unroll
        for (int kk = 0; kk < 4; kk++) {
            const int k0 = kk * 8;
            uint32_t a[MT][4];
#pragma unroll
            for (int mt = 0; mt < MT; mt++) {
                const float* pr = pB + (wr * 16 * MT + mt * 16 + ar) * PSROW + k0 + ak;
                a[mt][0] = __float_as_uint(pr[0]);
                a[mt][1] = __float_as_uint(pr[8 * PSROW]);
                a[mt][2] = __float_as_uint(pr[4]);
                a[mt][3] = __float_as_uint(pr[8 * PSROW + 4]);
            }
#pragma unroll
            for (int nt = 0; nt < 8; nt++) {
                const int n = wc * 64 + nt * 8 + ar;
                uint32_t b0 = __float_as_uint(wB[(k0 + ak) * WROW + n]);
                uint32_t b1 = __float_as_uint(wB[(k0 + ak + 4) * WROW + n]);
#pragma unroll
                for (int mt = 0; mt < MT; mt++)
                    mma_tf32(d[mt][nt], a[mt], b0, b1);
            }
        }
        __syncthreads();
    }
#pragma unroll
    for (int mt = 0; mt < MT; mt++) {
        const int r0 = wr * 16 * MT + mt * 16 + ar;
        const int r1 = r0 + 8;
        const int R0 = i0 + r0, R1 = i0 + r1;
        const size_t pb0 = packed_base(R0), pb1 = packed_base(R1);
#pragma unroll
        for (int nt = 0; nt < 8; nt++) {
            const int c = wc * 64 + nt * 8 + 2 * ak;
            float t0 = d[mt][nt][0], t1 = d[mt][nt][1];
            float t2 = d[mt][nt][2], t3 = d[mt][nt][3];
            *(float2*)(Cb + (size_t)R0 * FH + c) = make_float2(t0, t1);
            *(float2*)(Cb + (size_t)R1 * FH + c) = make_float2(t2, t3);
            Cpb[pb0 + (size_t)c * 4]       = __float2half_rn(t0);
            Cpb[pb0 + (size_t)(c + 1) * 4] = __float2half_rn(t1);
            Cpb[pb1 + (size_t)c * 4]       = __float2half_rn(t2);
            Cpb[pb1 + (size_t)(c + 1) * 4] = __float2half_rn(t3);
        }
    }
}

#define GEMM_SMEM(R) (2 * (R) * PSROW * 4 + 2 * 32 * WROW * 4)

// ---------------- K2: src/dst projections (exact fp32) -----------------------
__global__ void srcdst_kernel(const float* __restrict__ avec, int layer) {
    __shared__ float sa[2 * FH];
    const int b = blockIdx.y;
    const float* Wh = layer ? g_Wh2 : g_Wh1 + (size_t)b * NV * FH;
    const float* a  = avec + b * 2 * FH;
    float* src = layer ? g_src2 : g_src1 + b * NV;
    float* dst = layer ? g_dst2 : g_dst1 + b * NV;

    const int tid = threadIdx.x;
    for (int i = tid; i < 2 * FH; i += blockDim.x) sa[i] = a[i];
    __syncthreads();

    const int warp = tid >> 5, lane = tid & 31;
    const int row = blockIdx.x * 8 + warp;
    const float* wr = Wh + (size_t)row * FH;
    float s1 = 0.f, s2 = 0.f;
#pragma unroll
    for (int v = lane; v < FH; v += 32) {
        float w = wr[v];
        s1 += w * sa[v];
        s2 += w * sa[FH + v];
    }
#pragma unroll
    for (int o = 16; o; o >>= 1) {
        s1 += __shfl_xor_sync(0xffffffffu, s1, o);
        s2 += __shfl_xor_sync(0xffffffffu, s2, o);
    }
    if (lane == 0) { src[row] = s1; dst[row] = s2; }
}

// ---------------- K3: fp16 mma fused attention, KT=64 per phase --------------
// 128x256 tile, 512 threads, 16 warps (4x4), per-SMSP phase stagger,
// 64 neighbors per barrier (2 adj words, 64 MMA/warp, 16 exp/thread).
// NSPLIT=1: layer-0 (4 heads, full K, ELU->g_h1). NSPLIT=4: layer-1 partials.
#define ATTN_SMEM (2 * 128 * PSTW * 4 + 3 * 16 * WBW * 4 + 512 * 4)

template <int NSPLIT>
__global__ void __launch_bounds__(512, 1)
attn_kernel() {
    extern __shared__ char smem[];
    float* Ps    = (float*)smem;                          // [2][128*PSTW]
    float* Whs   = (float*)(smem + 2 * 128 * PSTW * 4);   // [3][16*WBW]
    float* lpart = (float*)(smem + 2 * 128 * PSTW * 4 + 3 * 16 * WBW * 4);
    const uint32_t whs_s = (uint32_t)__cvta_generic_to_shared(Whs);

    const int tid = threadIdx.x;
    const int wid = tid >> 5, lane = tid & 31;
    const int wr = wid >> 2, wc = wid & 3;
    const int i0 = blockIdx.x * 128;
    const bool mmaFirst = ((wid >> 2) & 1) != 0;   // per-SMSP 2/2 split

    const __half* WhP; const float* srcT; const float* dR;
    int jbase, NKT;
    if (NSPLIT > 1) {
        WhP = g_Wh2P; srcT = g_src2; dR = g_dst2;
        jbase = blockIdx.y * (NV / NSPLIT);
        NKT = (NV / NSPLIT) / 64;
    } else {
        const int b = blockIdx.z;
        WhP = g_Wh1P + (size_t)b * NV * FH;
        srcT = g_src1 + b * NV; dR = g_dst1 + b * NV;
        jbase = 0; NKT = NV / 64;
    }

    const int prow = tid >> 2;          // 0..127
    const int q_   = tid & 3;
    const float si = srcT[i0 + prow];
    const unsigned* adjrow = g_adjbits + (size_t)(i0 + prow) * NW + (jbase >> 5);
    const int ar = lane >> 2, ak = lane & 3;

    // cp.async mapping: thread -> (group row tid>>5 of 16, chunk tid&31)
    const __half* wsrc0 = WhP + (size_t)(jbase >> 5) * 8192 +
                          (size_t)(tid >> 5) * 1024 + (size_t)(tid & 31) * 8;
    const uint32_t wdst0 = whs_s +
                           (uint32_t)((tid >> 5) * WBW + (tid & 31) * 4) * 4u;

    float d[2][8][4];
#pragma unroll
    for (int mt = 0; mt < 2; mt++)
#pragma unroll
        for (int nt = 0; nt < 8; nt++)
#pragma unroll
            for (int v = 0; v < 4; v++) d[mt][nt][v] = 0.f;
    float lsum = 0.f;

    const int kb_ = (q_ < 2) ? 4 * q_ : 4 * q_ + 8;   // 0,4,16,20
    const int s_  = prow & 7;

#define COMPUTE_P(kt_, pbuf_)                                                 \
    {                                                                         \
        uint2* pr_ = (uint2*)((pbuf_) + prow * PSTW);                         \
        _Pragma("unroll")                                                     \
        for (int h_ = 0; h_ < 2; h_++) {                                      \
            const int j0_ = jbase + (kt_) * 64 + 32 * h_;                     \
            const unsigned aw_ = adjrow[2 * (kt_) + h_];                      \
            float4 dv1 = *(const float4*)(dR + j0_ + kb_);                    \
            float4 dv2 = *(const float4*)(dR + j0_ + kb_ + 8);                \
            float dd_[8] = {dv1.x, dv1.y, dv1.z, dv1.w,                       \
                            dv2.x, dv2.y, dv2.z, dv2.w};                      \
            float p_[8];                                                      \
            _Pragma("unroll")                                                 \
            for (int u_ = 0; u_ < 8; u_++) {                                  \
                float e_ = si + dd_[u_];                                      \
                e_ = fmaxf(e_, 0.2f * e_);                                    \
                float pp_ = __expf(e_);                                       \
                pp_ = fminf(pp_, 65000.f);                                    \
                const int bit_ = kb_ + ((u_ < 4) ? u_ : u_ + 4);              \
                pp_ = ((aw_ >> bit_) & 1u) ? pp_ : 0.f;                       \
                lsum += pp_;                                                  \
                p_[u_] = pp_;                                                 \
            }                                                                 \
            const int g0_ = 2 * q_;                                           \
            pr_[8 * h_ + (g0_ ^ s_)] =                                        \
                make_uint2(f2h2(p_[0], p_[1]), f2h2(p_[4], p_[5]));           \
            pr_[8 * h_ + ((g0_ + 1) ^ s_)] =                                  \
                make_uint2(f2h2(p_[2], p_[3]), f2h2(p_[6], p_[7]));           \
        }                                                                     \
    }

#define ISSUE_WH(kt_, buf_)                                                   \
    {                                                                         \
        const __half* wp_ = wsrc0 + (size_t)(kt_) * 16384;                    \
        const uint32_t wd_ = wdst0 + (uint32_t)(buf_) * (16u * WBW * 4u);     \
        _Pragma("unroll")                                                     \
        for (int q2_ = 0; q2_ < 4; q2_++)                                     \
            cp16(wd_ + q2_ * 512u, wp_ + q2_ * 256);                          \
    }

#define PREP_STEP(kt_)                                                        \
    {                                                                         \
        if ((kt_) + 2 < NKT) { ISSUE_WH((kt_) + 2, ((kt_) + 2) % 3); }        \
        cp_commit();                                                          \
        if ((kt_) + 1 < NKT) {                                                \
            COMPUTE_P((kt_) + 1, Ps + (((kt_) + 1) & 1) * 128 * PSTW);        \
        }                                                                     \
    }

#define MMA_STEP(kt_)                                                         \
    {                                                                         \
        const float* pB = Ps + ((kt_) & 1) * 128 * PSTW;                      \
        const float* wB = Whs + ((kt_) % 3) * 16 * WBW;                       \
        _Pragma("unroll")                                                     \
        for (int kk = 0; kk < 4; kk++) {                                      \
            const int gi_ = kk * 4 + ak;                                      \
            const int idx_ = (gi_ & 8) | ((gi_ & 7) ^ ar);                    \
            uint32_t a[2][4];                                                 \
            _Pragma("unroll")                                                 \
            for (int mt = 0; mt < 2; mt++) {                                  \
                const int row_ = wr * 32 + mt * 16 + ar;                      \
                uint2 u_ = ((const uint2*)(pB + row_ * PSTW))[idx_];          \
                uint2 v_ = ((const uint2*)(pB + (row_ + 8) * PSTW))[idx_];    \
                a[mt][0] = u_.x; a[mt][1] = v_.x;                             \
                a[mt][2] = u_.y; a[mt][3] = v_.y;                             \
            }                                                                 \
            _Pragma("unroll")                                                 \
            for (int nt = 0; nt < 8; nt++) {                                  \
                const int n = wc * 64 + nt * 8 + ar;                          \
                uint2 b_ = ((const uint2*)(wB + gi_ * WBW))[n];               \
                _Pragma("unroll")                                             \
                for (int mt = 0; mt < 2; mt++)                                \
                    mma_f16(d[mt][nt], a[mt], b_.x, b_.y);                    \
            }                                                                 \
        }                                                                     \
    }

    // ---- prologue ----
    ISSUE_WH(0, 0); cp_commit();
    if (1 < NKT) { ISSUE_WH(1, 1); }
    cp_commit();
    COMPUTE_P(0, Ps);

    for (int kt = 0; kt < NKT; kt++) {
        cp_wait1();          // Wh(kt) complete (per-thread)
        __syncthreads();     // visibility; prev MMA reads done
        if (mmaFirst) {
            MMA_STEP(kt);
            PREP_STEP(kt);
        } else {
            PREP_STEP(kt);
            MMA_STEP(kt);
        }
    }
    __syncthreads();
    lpart[tid] = lsum;       // lpart[prow*4 + q]
    __syncthreads();

    if (NSPLIT > 1) {
        float* np = g_np + (size_t)blockIdx.y * NV * FO;
#pragma unroll
        for (int mt = 0; mt < 2; mt++) {
            const int r0 = wr * 32 + mt * 16 + ar;
            const int r1 = r0 + 8;
#pragma unroll
            for (int nt = 0; nt < 8; nt++) {
                const int c = wc * 64 + nt * 8 + 2 * ak;
                *(float2*)(np + (size_t)(i0 + r0) * FO + c) = make_float2(d[mt][nt][0], d[mt][nt][1]);
                *(float2*)(np + (size_t)(i0 + r1) * FO + c) = make_float2(d[mt][nt][2], d[mt][nt][3]);
            }
        }
        if (tid < 128) {
            float l = lpart[tid * 4] + lpart[tid * 4 + 1] +
                      lpart[tid * 4 + 2] + lpart[tid * 4 + 3];
            g_lp[blockIdx.y * NV + i0 + tid] = l;
        }
    } else {
        float* out = g_h1;
        const int coloff = blockIdx.z * FH;
#pragma unroll
        for (int mt = 0; mt < 2; mt++) {
            const int r0 = wr * 32 + mt * 16 + ar;
            const int r1 = r0 + 8;
            const float l0 = lpart[r0*4] + lpart[r0*4+1] + lpart[r0*4+2] + lpart[r0*4+3];
            const float l1 = lpart[r1*4] + lpart[r1*4+1] + lpart[r1*4+2] + lpart[r1*4+3];
            const float rl0 = 1.0f / l0, rl1 = 1.0f / l1;
#pragma unroll
            for (int nt = 0; nt < 8; nt++) {
                const int c = coloff + wc * 64 + nt * 8 + 2 * ak;
                float o0 = d[mt][nt][0] * rl0, o1 = d[mt][nt][1] * rl0;
                float o2 = d[mt][nt][2] * rl1, o3 = d[mt][nt][3] * rl1;
                o0 = o0 > 0.f ? o0 : (__expf(o0) - 1.0f);
                o1 = o1 > 0.f ? o1 : (__expf(o1) - 1.0f);
                o2 = o2 > 0.f ? o2 : (__expf(o2) - 1.0f);
                o3 = o3 > 0.f ? o3 : (__expf(o3) - 1.0f);
                *(float2*)(out + (size_t)(i0 + r0) * F2 + c) = make_float2(o0, o1);
                *(float2*)(out + (size_t)(i0 + r1) * F2 + c) = make_float2(o2, o3);
            }
        }
    }
#undef COMPUTE_P
#undef ISSUE_WH
#undef PREP_STEP
#undef MMA_STEP
}

// ---------------- K4: combine 4 split partials (layer 1 epilogue) ------------
__global__ void combine_kernel(float* __restrict__ out) {
    const int i = blockIdx.x;
    const int c = threadIdx.x;
    float l = 0.f, n = 0.f;
#pragma unroll
    for (int s = 0; s < 4; s++) {
        l += g_lp[s * NV + i];
        n += g_np[(size_t)s * NV * FO + (size_t)i * FO + c];
    }
    out[(size_t)i * FO + c] = n / l;
}

// ---------------- launch -----------------------------------------------------
extern "C" void kernel_launch(void* const* d_in, const int* in_sizes, int n_in,
                              void* d_out, int out_size) {
    (void)in_sizes; (void)n_in; (void)out_size;
    const float* x   = (const float*)d_in[0];
    const int*   adj = (const int*)d_in[1];
    const float* W1  = (const float*)d_in[2];
    const float* a1  = (const float*)d_in[3];
    const float* W2  = (const float*)d_in[4];
    const float* a2  = (const float*)d_in[5];
    float* out = (float*)d_out;

    static int inited = 0;
    if (!inited) {
        cudaFuncSetAttribute(gemm_tf32_kernel<128>,
            cudaFuncAttributeMaxDynamicSharedMemorySize, GEMM_SMEM(128));
        cudaFuncSetAttribute(gemm_tf32_kernel<64>,
            cudaFuncAttributeMaxDynamicSharedMemorySize, GEMM_SMEM(64));
        cudaFuncSetAttribute(attn_kernel<1>,
            cudaFuncAttributeMaxDynamicSharedMemorySize, ATTN_SMEM);
        cudaFuncSetAttribute(attn_kernel<4>,
            cudaFuncAttributeMaxDynamicSharedMemorySize, ATTN_SMEM);
        inited = 1;
    }

    float*  Wh1p;  cudaGetSymbolAddress((void**)&Wh1p,  g_Wh1);
    __half* Wh1pp; cudaGetSymbolAddress((void**)&Wh1pp, g_Wh1P);
    float*  h1p;   cudaGetSymbolAddress((void**)&h1p,   g_h1);
    float*  Wh2p;  cudaGetSymbolAddress((void**)&Wh2p,  g_Wh2);
    __half* Wh2pp; cudaGetSymbolAddress((void**)&Wh2pp, g_Wh2P);

    adjbits_kernel<<<(NV * NV) / 256, 256>>>(adj);
    gemm_tf32_kernel<128><<<dim3(NV / 128, NHEADS), 512, GEMM_SMEM(128)>>>(
        x, W1, Wh1p, Wh1pp, F1, (long)F1 * FH, (long)NV * FH);
    srcdst_kernel<<<dim3(NV / 8, NHEADS), 256>>>(a1, 0);
    attn_kernel<1><<<dim3(NV / 128, 1, NHEADS), 512, ATTN_SMEM>>>();
    gemm_tf32_kernel<64><<<dim3(NV / 64, 1), 512, GEMM_SMEM(64)>>>(
        h1p, W2, Wh2p, Wh2pp, F2, 0L, 0L);
    srcdst_kernel<<<dim3(NV / 8, 1), 256>>>(a2, 1);
    attn_kernel<4><<<dim3(NV / 128, 4), 512, ATTN_SMEM>>>();
    combine_kernel<<<NV, 256>>>(out);
}